// round 2
// baseline (speedup 1.0000x reference)
#include <cuda_runtime.h>
#include <cuda_bf16.h>

// Problem constants
// B=2, S=2048, D=1024, H=16, DK=64, SP=128, PD=3
// M = B*S = 4096 rows for every projection GEMM.

#define MROWS 4096
#define DIM   1024
#define HEADS 16
#define DKH   64
#define SEQ   2048

// ---------------------------------------------------------------------------
// Scratch (device globals; no allocation allowed)
// ---------------------------------------------------------------------------
__device__ float g_Q[MROWS * DIM];
__device__ float g_K[MROWS * DIM];
__device__ float g_V[MROWS * DIM];
__device__ float g_ctx[MROWS * DIM];

// ---------------------------------------------------------------------------
// SGEMM: C[4096,1024] = A[4096,1024] @ W[1024,1024] + bias
// Optional physics epilogue (K projection): folds pb * (physics @ Pw)
// reshaped to [B, SP*H, DK] into K, so attention becomes plain MHA.
//   add = pb * sum_p phys[b, s/16, p] * Pw[p, (s%16)*64 + (n%64)]
// 128x128 tile, BK=16, 256 threads, 8x8 microtile.
// ---------------------------------------------------------------------------
__global__ __launch_bounds__(256)
void sgemm4096_kernel(const float* __restrict__ A, const float* __restrict__ W,
                      const float* __restrict__ bias, float* __restrict__ C,
                      const float* __restrict__ phys, const float* __restrict__ Pw,
                      const float* __restrict__ pb) {
    __shared__ float As[16 * 128];   // As[k][m] (transposed A tile)
    __shared__ float Bs[16 * 128];   // Bs[k][n]

    const int t   = threadIdx.x;
    const int n0  = blockIdx.x * 128;
    const int m0  = blockIdx.y * 128;
    const int tty = t >> 4;          // 0..15 -> rows tty*8..+7
    const int ttx = t & 15;          // 0..15 -> cols ttx*8..+7

    float acc[8][8];
#pragma unroll
    for (int i = 0; i < 8; i++)
#pragma unroll
        for (int j = 0; j < 8; j++) acc[i][j] = 0.f;

    // Load mapping
    const int ar = t >> 2;            // 0..63
    const int ac = (t & 3) << 2;      // 0,4,8,12
    const int br = t >> 5;            // 0..7
    const int bc = (t & 31) << 2;     // 0..124

    const float* Ap = A + (size_t)(m0 + ar) * DIM + ac;
    const float* Wp = W + (size_t)br * DIM + n0 + bc;

    for (int k0 = 0; k0 < DIM; k0 += 16) {
        __syncthreads();
        // A tile: rows ar and ar+64, cols k0+ac..+3, store transposed
        float4 a0 = *(const float4*)(Ap + k0);
        float4 a1 = *(const float4*)(Ap + (size_t)64 * DIM + k0);
        As[(ac + 0) * 128 + ar] = a0.x;
        As[(ac + 1) * 128 + ar] = a0.y;
        As[(ac + 2) * 128 + ar] = a0.z;
        As[(ac + 3) * 128 + ar] = a0.w;
        As[(ac + 0) * 128 + ar + 64] = a1.x;
        As[(ac + 1) * 128 + ar + 64] = a1.y;
        As[(ac + 2) * 128 + ar + 64] = a1.z;
        As[(ac + 3) * 128 + ar + 64] = a1.w;
        // B tile: rows k0+br and k0+br+8
        float4 b0 = *(const float4*)(Wp + (size_t)k0 * DIM);
        float4 b1 = *(const float4*)(Wp + (size_t)(k0 + 8) * DIM);
        *(float4*)&Bs[br * 128 + bc]       = b0;
        *(float4*)&Bs[(br + 8) * 128 + bc] = b1;
        __syncthreads();

#pragma unroll
        for (int k = 0; k < 16; k++) {
            float4 av0 = *(float4*)&As[k * 128 + tty * 8];
            float4 av1 = *(float4*)&As[k * 128 + tty * 8 + 4];
            float4 bv0 = *(float4*)&Bs[k * 128 + ttx * 8];
            float4 bv1 = *(float4*)&Bs[k * 128 + ttx * 8 + 4];
            float a[8] = {av0.x, av0.y, av0.z, av0.w, av1.x, av1.y, av1.z, av1.w};
            float bb[8] = {bv0.x, bv0.y, bv0.z, bv0.w, bv1.x, bv1.y, bv1.z, bv1.w};
#pragma unroll
            for (int i = 0; i < 8; i++)
#pragma unroll
                for (int j = 0; j < 8; j++) acc[i][j] += a[i] * bb[j];
        }
    }

    // Epilogue
    const float pbv = phys ? pb[0] : 0.f;
#pragma unroll
    for (int i = 0; i < 8; i++) {
        const int m = m0 + tty * 8 + i;
        float p0 = 0.f, p1 = 0.f, p2 = 0.f;
        int jjbase = 0;
        if (phys) {
            const int bi = m >> 11;         // batch
            const int s  = m & 2047;        // seq pos
            const float* ph = phys + (size_t)((bi << 7) + (s >> 4)) * 3;
            p0 = ph[0]; p1 = ph[1]; p2 = ph[2];
            jjbase = (s & 15) << 6;
        }
        float out[8];
#pragma unroll
        for (int j = 0; j < 8; j++) {
            const int n = n0 + ttx * 8 + j;
            float v = acc[i][j] + bias[n];
            if (phys) {
                const int jj = jjbase + (n & 63);
                v += pbv * (p0 * Pw[jj] + p1 * Pw[1024 + jj] + p2 * Pw[2048 + jj]);
            }
            out[j] = v;
        }
        float* Cp = C + (size_t)m * DIM + n0 + ttx * 8;
        *(float4*)(Cp)     = make_float4(out[0], out[1], out[2], out[3]);
        *(float4*)(Cp + 4) = make_float4(out[4], out[5], out[6], out[7]);
    }
}

// ---------------------------------------------------------------------------
// Flash attention (fp32): one CTA per (b, h, q-tile of 128).
// K/V tiles of 64 rows. Online softmax; O accumulators in registers.
//
// SMEM layout (floats):
//   Qt [64][132]  : Q tile transposed (d-major)       off 0      sz 8448
//   Ks [64][68]   : K tile (k-major, d contiguous)    off 8448   sz 4352
//   Vs [64][68]   : V tile (k-major, d contiguous)    off 12800  sz 4352
//   Ps [128][68]  : S/P tile                          off 17152  sz 8704
//   m  [128]                                          off 25856
//   l  [128]                                          off 25984
//   alpha [128]                                       off 26112
// total 26240 floats = 104960 bytes (dynamic)
// ---------------------------------------------------------------------------
#define ATTN_SMEM_BYTES (26240 * 4)

__global__ __launch_bounds__(256)
void attn_kernel(const float* __restrict__ Q, const float* __restrict__ K,
                 const float* __restrict__ V, float* __restrict__ O) {
    extern __shared__ float sm[];
    float* Qt   = sm;               // [64][132]
    float* Ks   = sm + 8448;        // [64][68]
    float* Vs   = sm + 12800;       // [64][68]
    float* Ps   = sm + 17152;       // [128][68]
    float* mrow = sm + 25856;
    float* lrow = sm + 25984;
    float* arow = sm + 26112;

    const int t  = threadIdx.x;
    const int qb = blockIdx.x;      // 0..15
    const int h  = blockIdx.y;      // 0..15
    const int b  = blockIdx.z;      // 0..1
    const int q0 = qb * 128;

    const float* Qg = Q + ((size_t)(b * SEQ + q0)) * DIM + h * DKH;
    const float* Kg = K + ((size_t)b * SEQ) * DIM + h * DKH;
    const float* Vg = V + ((size_t)b * SEQ) * DIM + h * DKH;

    // Load Q tile transposed: 128 rows x 64 cols
    for (int idx = t; idx < 2048; idx += 256) {
        const int q = idx >> 4;
        const int d = (idx & 15) << 2;
        float4 v = *(const float4*)(Qg + (size_t)q * DIM + d);
        Qt[(d + 0) * 132 + q] = v.x;
        Qt[(d + 1) * 132 + q] = v.y;
        Qt[(d + 2) * 132 + q] = v.z;
        Qt[(d + 3) * 132 + q] = v.w;
    }
    if (t < 128) { mrow[t] = -3.0e38f; lrow[t] = 0.f; }

    // GEMM1 mapping: q = sy*4+i (sy 0..31), k = sx*8+j (sx 0..7)  -> 128x64 tile
    const int sy = t >> 3, sx = t & 7;
    // GEMM2 / output mapping: q = ty*8+i (ty 0..15), dk = tx*4+j (tx 0..15)
    const int ty = t >> 4, tx = t & 15;
    float oacc[8][4];
#pragma unroll
    for (int i = 0; i < 8; i++)
#pragma unroll
        for (int j = 0; j < 4; j++) oacc[i][j] = 0.f;

    for (int kt = 0; kt < SEQ / 64; kt++) {
        __syncthreads();   // previous GEMM2 done reading Ps/Vs; Qt/m/l ready (iter 0)

        // Load K,V tiles (64x64 each)
        const float* Kt0 = Kg + (size_t)(kt * 64) * DIM;
        const float* Vt0 = Vg + (size_t)(kt * 64) * DIM;
        for (int idx = t; idx < 1024; idx += 256) {
            const int r = idx >> 4;
            const int d = (idx & 15) << 2;
            *(float4*)&Ks[r * 68 + d] = *(const float4*)(Kt0 + (size_t)r * DIM + d);
            *(float4*)&Vs[r * 68 + d] = *(const float4*)(Vt0 + (size_t)r * DIM + d);
        }
        __syncthreads();

        // GEMM1: S[q = sy*4+i][k = sx*8+j] = Q[q] . K[k]
        float sacc[4][8];
#pragma unroll
        for (int i = 0; i < 4; i++)
#pragma unroll
            for (int j = 0; j < 8; j++) sacc[i][j] = 0.f;

#pragma unroll 16
        for (int d = 0; d < 64; d++) {
            float4 qv = *(float4*)&Qt[d * 132 + sy * 4];
            float kreg[8];
#pragma unroll
            for (int j = 0; j < 8; j++) kreg[j] = Ks[(sx * 8 + j) * 68 + d];
#pragma unroll
            for (int j = 0; j < 8; j++) {
                sacc[0][j] += qv.x * kreg[j];
                sacc[1][j] += qv.y * kreg[j];
                sacc[2][j] += qv.z * kreg[j];
                sacc[3][j] += qv.w * kreg[j];
            }
        }
        // Write scaled scores (inv = 1/sqrt(64) = 0.125)
#pragma unroll
        for (int i = 0; i < 4; i++) {
            float* row = &Ps[(sy * 4 + i) * 68 + sx * 8];
            *(float4*)(row)     = make_float4(sacc[i][0] * 0.125f, sacc[i][1] * 0.125f,
                                              sacc[i][2] * 0.125f, sacc[i][3] * 0.125f);
            *(float4*)(row + 4) = make_float4(sacc[i][4] * 0.125f, sacc[i][5] * 0.125f,
                                              sacc[i][6] * 0.125f, sacc[i][7] * 0.125f);
        }
        __syncthreads();

        // Online softmax: thread -> row q = t>>1, half = t&1 (32 cols each)
        {
            const int q = t >> 1, half = t & 1;
            float* row = &Ps[q * 68 + half * 32];
            float mloc = -3.0e38f;
#pragma unroll
            for (int j = 0; j < 32; j++) mloc = fmaxf(mloc, row[j]);
            mloc = fmaxf(mloc, __shfl_xor_sync(0xffffffffu, mloc, 1));
            const float mold = mrow[q];
            const float mnew = fmaxf(mold, mloc);
            float ssum = 0.f;
#pragma unroll
            for (int j = 0; j < 32; j++) {
                float p = __expf(row[j] - mnew);
                row[j] = p;
                ssum += p;
            }
            ssum += __shfl_xor_sync(0xffffffffu, ssum, 1);
            if (half == 0) {
                const float a = __expf(mold - mnew);   // 0 on first tile
                lrow[q] = lrow[q] * a + ssum;
                mrow[q] = mnew;
                arow[q] = a;
            }
        }
        __syncthreads();

        // Rescale O, then GEMM2: O[q][dk] += P[q][kk] * V[kk][dk]
#pragma unroll
        for (int i = 0; i < 8; i++) {
            const float a = arow[ty * 8 + i];
#pragma unroll
            for (int j = 0; j < 4; j++) oacc[i][j] *= a;
        }
#pragma unroll 16
        for (int kk = 0; kk < 64; kk++) {
            float4 vv = *(float4*)&Vs[kk * 68 + tx * 4];
#pragma unroll
            for (int i = 0; i < 8; i++) {
                const float p = Ps[(ty * 8 + i) * 68 + kk];
                oacc[i][0] += p * vv.x;
                oacc[i][1] += p * vv.y;
                oacc[i][2] += p * vv.z;
                oacc[i][3] += p * vv.w;
            }
        }
    }

    // Epilogue: normalize by l and store ctx[b, q0+q, h*64 + dk]
#pragma unroll
    for (int i = 0; i < 8; i++) {
        const int q = ty * 8 + i;
        const float li = 1.f / lrow[q];
        float* Op = O + ((size_t)(b * SEQ + q0 + q)) * DIM + h * DKH + tx * 4;
        *(float4*)Op = make_float4(oacc[i][0] * li, oacc[i][1] * li,
                                   oacc[i][2] * li, oacc[i][3] * li);
    }
}

// ---------------------------------------------------------------------------
// Launch
// ---------------------------------------------------------------------------
extern "C" void kernel_launch(void* const* d_in, const int* in_sizes, int n_in,
                              void* d_out, int out_size) {
    const float* query  = (const float*)d_in[0];
    const float* key_in = (const float*)d_in[1];
    const float* value  = (const float*)d_in[2];
    const float* phys   = (const float*)d_in[3];
    const float* Wq     = (const float*)d_in[4];
    const float* bq     = (const float*)d_in[5];
    const float* Wk     = (const float*)d_in[6];
    const float* bk     = (const float*)d_in[7];
    const float* Wv     = (const float*)d_in[8];
    const float* bv     = (const float*)d_in[9];
    const float* Wo     = (const float*)d_in[10];
    const float* bo     = (const float*)d_in[11];
    const float* Pw     = (const float*)d_in[12];
    const float* pb     = (const float*)d_in[13];
    float* out          = (float*)d_out;

    float *pQ, *pK, *pV, *pC;
    cudaGetSymbolAddress((void**)&pQ, g_Q);
    cudaGetSymbolAddress((void**)&pK, g_K);
    cudaGetSymbolAddress((void**)&pV, g_V);
    cudaGetSymbolAddress((void**)&pC, g_ctx);

    cudaFuncSetAttribute(attn_kernel, cudaFuncAttributeMaxDynamicSharedMemorySize,
                         ATTN_SMEM_BYTES);

    dim3 gg(DIM / 128, MROWS / 128);   // (8, 32)
    // Projections (physics folded into K)
    sgemm4096_kernel<<<gg, 256>>>(query,  Wq, bq, pQ, nullptr, nullptr, nullptr);
    sgemm4096_kernel<<<gg, 256>>>(key_in, Wk, bk, pK, phys, Pw, pb);
    sgemm4096_kernel<<<gg, 256>>>(value,  Wv, bv, pV, nullptr, nullptr, nullptr);
    // Attention
    dim3 ga(SEQ / 128, HEADS, 2);      // (16, 16, 2)
    attn_kernel<<<ga, 256, ATTN_SMEM_BYTES>>>(pQ, pK, pV, pC);
    // Output projection
    sgemm4096_kernel<<<gg, 256>>>(pC, Wo, bo, out, nullptr, nullptr, nullptr);
}

// round 4
// speedup vs baseline: 4.1751x; 4.1751x over previous
#include <cuda_runtime.h>
#include <cuda_bf16.h>
#include <cstdint>

#define MROWS 4096
#define DIM   1024
#define HEADS 16
#define DKH   64
#define SEQ   2048

// ---------------------------------------------------------------------------
// Scratch (device globals; no allocation allowed)
// ---------------------------------------------------------------------------
__device__ float g_Q[MROWS * DIM];
__device__ float g_K[MROWS * DIM];
__device__ float g_V[MROWS * DIM];
__device__ float g_ctx[MROWS * DIM];

// ---------------------------------------------------------------------------
// Helpers
// ---------------------------------------------------------------------------
__device__ __forceinline__ unsigned f2tf(float f) {
    unsigned r;
    asm("cvt.rna.tf32.f32 %0, %1;" : "=r"(r) : "f"(f));
    return r;
}
__device__ __forceinline__ void mma_tf32(float c[4], unsigned a0, unsigned a1,
                                         unsigned a2, unsigned a3,
                                         unsigned b0, unsigned b1) {
    asm volatile(
        "mma.sync.aligned.m16n8k8.row.col.f32.tf32.tf32.f32 "
        "{%0,%1,%2,%3}, {%4,%5,%6,%7}, {%8,%9}, {%0,%1,%2,%3};"
        : "+f"(c[0]), "+f"(c[1]), "+f"(c[2]), "+f"(c[3])
        : "r"(a0), "r"(a1), "r"(a2), "r"(a3), "r"(b0), "r"(b1));
}

// ---------------------------------------------------------------------------
// TF32 SGEMM: C[4096,1024] = A[4096,1024] @ W[1024,1024] + bias (+ physics)
// 128x128x32 CTA tile, 8 warps (2m x 4n), 64x32 warp tile, m16n8k8 HMMA.
// As[m][k] stride 36 (4*gr+gc conflict-free); Bs[k][n] stride 136 (8*gc+gr).
// ---------------------------------------------------------------------------
__global__ __launch_bounds__(256)
void sgemm_tf32_kernel(const float* __restrict__ A, const float* __restrict__ W,
                       const float* __restrict__ bias, float* __restrict__ C,
                       const float* __restrict__ phys, const float* __restrict__ Pw,
                       const float* __restrict__ pb) {
    __shared__ unsigned As[128 * 36];
    __shared__ unsigned Bs[32 * 136];

    const int t    = threadIdx.x;
    const int w    = t >> 5;
    const int lane = t & 31;
    const int wm   = w >> 2;          // 0..1
    const int wn   = w & 3;           // 0..3
    const int gr   = lane >> 2;       // 0..7
    const int gc   = lane & 3;        // 0..3
    const int n0   = blockIdx.x * 128;
    const int m0   = blockIdx.y * 128;

    float c[4][4][4];
#pragma unroll
    for (int mi = 0; mi < 4; mi++)
#pragma unroll
        for (int ni = 0; ni < 4; ni++)
#pragma unroll
            for (int r = 0; r < 4; r++) c[mi][ni][r] = 0.f;

    // global load mapping
    const int am_r = t >> 1;             // 0..127
    const int am_c = (t & 1) * 16;       // 0 or 16
    const int bk_r = t >> 3;             // 0..31
    const int bk_c = (t & 7) * 16;       // 0..120
    const float* Ap = A + (size_t)(m0 + am_r) * DIM + am_c;
    const float* Wp = W + (size_t)bk_r * DIM + n0 + bk_c;

    for (int k0 = 0; k0 < DIM; k0 += 32) {
        float4 av[4], bv[4];
#pragma unroll
        for (int j = 0; j < 4; j++) {
            av[j] = *(const float4*)(Ap + k0 + j * 4);
            bv[j] = *(const float4*)(Wp + (size_t)k0 * DIM + j * 4);
        }
        __syncthreads();
#pragma unroll
        for (int j = 0; j < 4; j++) {
            uint4 at = make_uint4(f2tf(av[j].x), f2tf(av[j].y), f2tf(av[j].z), f2tf(av[j].w));
            uint4 bt = make_uint4(f2tf(bv[j].x), f2tf(bv[j].y), f2tf(bv[j].z), f2tf(bv[j].w));
            *(uint4*)&As[am_r * 36 + am_c + j * 4] = at;
            *(uint4*)&Bs[bk_r * 136 + bk_c + j * 4] = bt;
        }
        __syncthreads();

#pragma unroll
        for (int ks = 0; ks < 4; ks++) {
            unsigned a[4][4];
#pragma unroll
            for (int mi = 0; mi < 4; mi++) {
                const int mr = wm * 64 + mi * 16 + gr;
                a[mi][0] = As[mr * 36 + ks * 8 + gc];
                a[mi][1] = As[(mr + 8) * 36 + ks * 8 + gc];
                a[mi][2] = As[mr * 36 + ks * 8 + gc + 4];
                a[mi][3] = As[(mr + 8) * 36 + ks * 8 + gc + 4];
            }
            unsigned b[4][2];
#pragma unroll
            for (int ni = 0; ni < 4; ni++) {
                const int nc = wn * 32 + ni * 8 + gr;
                b[ni][0] = Bs[(ks * 8 + gc) * 136 + nc];
                b[ni][1] = Bs[(ks * 8 + gc + 4) * 136 + nc];
            }
#pragma unroll
            for (int mi = 0; mi < 4; mi++)
#pragma unroll
                for (int ni = 0; ni < 4; ni++)
                    mma_tf32(c[mi][ni], a[mi][0], a[mi][1], a[mi][2], a[mi][3],
                             b[ni][0], b[ni][1]);
        }
    }

    // Epilogue: bias (+ optional physics fold for K projection)
    const float pbv = phys ? pb[0] : 0.f;
#pragma unroll
    for (int mi = 0; mi < 4; mi++) {
#pragma unroll
        for (int h2 = 0; h2 < 2; h2++) {
            const int m = m0 + wm * 64 + mi * 16 + gr + h2 * 8;
            float p0 = 0.f, p1 = 0.f, p2 = 0.f;
            int jjb = 0;
            if (phys) {
                const int bi = m >> 11;
                const int s  = m & 2047;
                const float* ph = phys + (size_t)((bi << 7) + (s >> 4)) * 3;
                p0 = ph[0]; p1 = ph[1]; p2 = ph[2];
                jjb = (s & 15) << 6;
            }
#pragma unroll
            for (int ni = 0; ni < 4; ni++) {
                const int n = n0 + wn * 32 + ni * 8 + 2 * gc;
                float v0 = c[mi][ni][h2 * 2 + 0] + bias[n];
                float v1 = c[mi][ni][h2 * 2 + 1] + bias[n + 1];
                if (phys) {
                    const int j0 = jjb + (n & 63);
                    v0 += pbv * (p0 * Pw[j0]     + p1 * Pw[1024 + j0]     + p2 * Pw[2048 + j0]);
                    v1 += pbv * (p0 * Pw[j0 + 1] + p1 * Pw[1024 + j0 + 1] + p2 * Pw[2048 + j0 + 1]);
                }
                *(float2*)&C[(size_t)m * DIM + n] = make_float2(v0, v1);
            }
        }
    }
}

// ---------------------------------------------------------------------------
// Flash attention, TF32 mma, register-resident online softmax.
// One CTA per (b, h, 128-row q tile); 8 warps, warp owns 16 q rows.
// K/V tiles of 64. SMEM (floats): Qs[128][68] | Ks[64][68] | Vs[64][72] | Ps[128][68]
// ---------------------------------------------------------------------------
#define QS_OFF 0
#define KS_OFF 8704
#define VS_OFF 13056
#define PS_OFF 17664
#define ATTN_SMEM_BYTES ((17664 + 128 * 68) * 4)   // 105472 bytes

__global__ __launch_bounds__(256)
void attn_tf32_kernel(const float* __restrict__ Q, const float* __restrict__ K,
                      const float* __restrict__ V, float* __restrict__ O) {
    extern __shared__ unsigned sm_u[];
    unsigned* Qs = sm_u + QS_OFF;   // [128][68]
    unsigned* Ks = sm_u + KS_OFF;   // [64][68]
    unsigned* Vs = sm_u + VS_OFF;   // [64][72]
    unsigned* Ps = sm_u + PS_OFF;   // [128][68]

    const int t    = threadIdx.x;
    const int w    = t >> 5;
    const int lane = t & 31;
    const int gr   = lane >> 2;     // 0..7
    const int gc   = lane & 3;      // 0..3
    const int qw   = w * 16;        // warp q base in tile
    const int qb   = blockIdx.x;
    const int h    = blockIdx.y;
    const int b    = blockIdx.z;
    const int q0   = qb * 128;

    const float* Qg = Q + ((size_t)(b * SEQ + q0)) * DIM + h * DKH;
    const float* Kg = K + ((size_t)b * SEQ) * DIM + h * DKH;
    const float* Vg = V + ((size_t)b * SEQ) * DIM + h * DKH;

    // Load Q tile [128][64] -> tf32
    for (int i = t; i < 2048; i += 256) {
        const int q = i >> 4;
        const int d = (i & 15) << 2;
        float4 v = *(const float4*)(Qg + (size_t)q * DIM + d);
        *(uint4*)&Qs[q * 68 + d] = make_uint4(f2tf(v.x), f2tf(v.y), f2tf(v.z), f2tf(v.w));
    }

    // per-thread online softmax state: rows (qw+gr) and (qw+gr+8)
    float m0 = -1e30f, m1 = -1e30f, l0 = 0.f, l1 = 0.f;
    float o[8][4];
#pragma unroll
    for (int di = 0; di < 8; di++)
#pragma unroll
        for (int r = 0; r < 4; r++) o[di][r] = 0.f;

    for (int kt = 0; kt < SEQ / 64; kt++) {
        __syncthreads();   // K/V (and Qs on iter 0) safe to (re)write
        const float* Kt0 = Kg + (size_t)(kt * 64) * DIM;
        const float* Vt0 = Vg + (size_t)(kt * 64) * DIM;
        for (int i = t; i < 1024; i += 256) {
            const int r = i >> 4;
            const int d = (i & 15) << 2;
            float4 kv = *(const float4*)(Kt0 + (size_t)r * DIM + d);
            float4 vv = *(const float4*)(Vt0 + (size_t)r * DIM + d);
            *(uint4*)&Ks[r * 68 + d] = make_uint4(f2tf(kv.x), f2tf(kv.y), f2tf(kv.z), f2tf(kv.w));
            *(uint4*)&Vs[r * 72 + d] = make_uint4(f2tf(vv.x), f2tf(vv.y), f2tf(vv.z), f2tf(vv.w));
        }
        __syncthreads();

        // GEMM1: S[16q x 64k] for this warp
        float s[8][4];
#pragma unroll
        for (int ni = 0; ni < 8; ni++)
#pragma unroll
            for (int r = 0; r < 4; r++) s[ni][r] = 0.f;

#pragma unroll
        for (int ks = 0; ks < 8; ks++) {
            const unsigned a0 = Qs[(qw + gr) * 68 + ks * 8 + gc];
            const unsigned a1 = Qs[(qw + gr + 8) * 68 + ks * 8 + gc];
            const unsigned a2 = Qs[(qw + gr) * 68 + ks * 8 + gc + 4];
            const unsigned a3 = Qs[(qw + gr + 8) * 68 + ks * 8 + gc + 4];
#pragma unroll
            for (int ni = 0; ni < 8; ni++) {
                const unsigned b0 = Ks[(ni * 8 + gr) * 68 + ks * 8 + gc];
                const unsigned b1 = Ks[(ni * 8 + gr) * 68 + ks * 8 + gc + 4];
                mma_tf32(s[ni], a0, a1, a2, a3, b0, b1);
            }
        }

        // Online softmax in registers (rows r=qw+gr -> c0/c1, r+8 -> c2/c3)
        float mx0 = -1e30f, mx1 = -1e30f;
#pragma unroll
        for (int ni = 0; ni < 8; ni++) {
            s[ni][0] *= 0.125f; s[ni][1] *= 0.125f;
            s[ni][2] *= 0.125f; s[ni][3] *= 0.125f;
            mx0 = fmaxf(mx0, fmaxf(s[ni][0], s[ni][1]));
            mx1 = fmaxf(mx1, fmaxf(s[ni][2], s[ni][3]));
        }
        mx0 = fmaxf(mx0, __shfl_xor_sync(0xffffffffu, mx0, 1));
        mx0 = fmaxf(mx0, __shfl_xor_sync(0xffffffffu, mx0, 2));
        mx1 = fmaxf(mx1, __shfl_xor_sync(0xffffffffu, mx1, 1));
        mx1 = fmaxf(mx1, __shfl_xor_sync(0xffffffffu, mx1, 2));
        const float mn0 = fmaxf(m0, mx0), mn1 = fmaxf(m1, mx1);
        const float al0 = __expf(m0 - mn0), al1 = __expf(m1 - mn1);
        m0 = mn0; m1 = mn1;
        float rs0 = 0.f, rs1 = 0.f;
#pragma unroll
        for (int ni = 0; ni < 8; ni++) {
            s[ni][0] = __expf(s[ni][0] - mn0);
            s[ni][1] = __expf(s[ni][1] - mn0);
            s[ni][2] = __expf(s[ni][2] - mn1);
            s[ni][3] = __expf(s[ni][3] - mn1);
            rs0 += s[ni][0] + s[ni][1];
            rs1 += s[ni][2] + s[ni][3];
        }
        rs0 += __shfl_xor_sync(0xffffffffu, rs0, 1);
        rs0 += __shfl_xor_sync(0xffffffffu, rs0, 2);
        rs1 += __shfl_xor_sync(0xffffffffu, rs1, 1);
        rs1 += __shfl_xor_sync(0xffffffffu, rs1, 2);
        l0 = l0 * al0 + rs0;
        l1 = l1 * al1 + rs1;

        // Write P (tf32) to warp-private Ps rows
#pragma unroll
        for (int ni = 0; ni < 8; ni++) {
            *(uint2*)&Ps[(qw + gr) * 68 + ni * 8 + 2 * gc] =
                make_uint2(f2tf(s[ni][0]), f2tf(s[ni][1]));
            *(uint2*)&Ps[(qw + gr + 8) * 68 + ni * 8 + 2 * gc] =
                make_uint2(f2tf(s[ni][2]), f2tf(s[ni][3]));
        }

        // Rescale O accumulators
#pragma unroll
        for (int di = 0; di < 8; di++) {
            o[di][0] *= al0; o[di][1] *= al0;
            o[di][2] *= al1; o[di][3] *= al1;
        }
        __syncwarp();

        // GEMM2: O[16q x 64d] += P[16q x 64k] @ V[64k x 64d]
#pragma unroll
        for (int ks = 0; ks < 8; ks++) {
            const unsigned a0 = Ps[(qw + gr) * 68 + ks * 8 + gc];
            const unsigned a1 = Ps[(qw + gr + 8) * 68 + ks * 8 + gc];
            const unsigned a2 = Ps[(qw + gr) * 68 + ks * 8 + gc + 4];
            const unsigned a3 = Ps[(qw + gr + 8) * 68 + ks * 8 + gc + 4];
#pragma unroll
            for (int di = 0; di < 8; di++) {
                const unsigned b0 = Vs[(ks * 8 + gc) * 72 + di * 8 + gr];
                const unsigned b1 = Vs[(ks * 8 + gc + 4) * 72 + di * 8 + gr];
                mma_tf32(o[di], a0, a1, a2, a3, b0, b1);
            }
        }
    }

    // Epilogue: normalize and store
    const float i0 = 1.f / l0, i1 = 1.f / l1;
    const size_t r0 = (size_t)(b * SEQ + q0 + qw + gr) * DIM + h * DKH;
    const size_t r1 = (size_t)(b * SEQ + q0 + qw + gr + 8) * DIM + h * DKH;
#pragma unroll
    for (int di = 0; di < 8; di++) {
        const int col = di * 8 + 2 * gc;
        *(float2*)&O[r0 + col] = make_float2(o[di][0] * i0, o[di][1] * i0);
        *(float2*)&O[r1 + col] = make_float2(o[di][2] * i1, o[di][3] * i1);
    }
}

// ---------------------------------------------------------------------------
// Launch
// ---------------------------------------------------------------------------
extern "C" void kernel_launch(void* const* d_in, const int* in_sizes, int n_in,
                              void* d_out, int out_size) {
    const float* query  = (const float*)d_in[0];
    const float* key_in = (const float*)d_in[1];
    const float* value  = (const float*)d_in[2];
    const float* phys   = (const float*)d_in[3];
    const float* Wq     = (const float*)d_in[4];
    const float* bq     = (const float*)d_in[5];
    const float* Wk     = (const float*)d_in[6];
    const float* bk     = (const float*)d_in[7];
    const float* Wv     = (const float*)d_in[8];
    const float* bv     = (const float*)d_in[9];
    const float* Wo     = (const float*)d_in[10];
    const float* bo     = (const float*)d_in[11];
    const float* Pw     = (const float*)d_in[12];
    const float* pb     = (const float*)d_in[13];
    float* out          = (float*)d_out;

    float *pQ, *pK, *pV, *pC;
    cudaGetSymbolAddress((void**)&pQ, g_Q);
    cudaGetSymbolAddress((void**)&pK, g_K);
    cudaGetSymbolAddress((void**)&pV, g_V);
    cudaGetSymbolAddress((void**)&pC, g_ctx);

    cudaFuncSetAttribute(attn_tf32_kernel, cudaFuncAttributeMaxDynamicSharedMemorySize,
                         ATTN_SMEM_BYTES);

    dim3 gg(DIM / 128, MROWS / 128);   // (8, 32)
    sgemm_tf32_kernel<<<gg, 256>>>(query,  Wq, bq, pQ, nullptr, nullptr, nullptr);
    sgemm_tf32_kernel<<<gg, 256>>>(key_in, Wk, bk, pK, phys, Pw, pb);
    sgemm_tf32_kernel<<<gg, 256>>>(value,  Wv, bv, pV, nullptr, nullptr, nullptr);

    dim3 ga(SEQ / 128, HEADS, 2);      // (16, 16, 2)
    attn_tf32_kernel<<<ga, 256, ATTN_SMEM_BYTES>>>(pQ, pK, pV, pC);

    sgemm_tf32_kernel<<<gg, 256>>>(pC, Wo, bo, out, nullptr, nullptr, nullptr);
}

// round 6
// speedup vs baseline: 6.3572x; 1.5227x over previous
#include <cuda_runtime.h>
#include <cuda_bf16.h>
#include <cstdint>

#define MROWS 4096
#define DIM   1024
#define HEADS 16
#define DKH   64
#define SEQ   2048
#define NELEM (MROWS * DIM)
#define WELEM (DIM * DIM)

// ---------------------------------------------------------------------------
// Scratch (device globals; no allocation allowed). All tf32 payloads as u32.
// ---------------------------------------------------------------------------
__device__ unsigned g_Q[NELEM];
__device__ unsigned g_K[NELEM];
__device__ unsigned g_V[NELEM];
__device__ unsigned g_ctx[NELEM];
__device__ unsigned g_tA0[NELEM];    // query  (tf32)
__device__ unsigned g_tA1[NELEM];    // key_in (tf32)
__device__ unsigned g_tA2[NELEM];    // value  (tf32)
__device__ unsigned g_tW[4 * WELEM]; // Wq,Wk,Wv,Wo (tf32)

// ---------------------------------------------------------------------------
// Helpers
// ---------------------------------------------------------------------------
__device__ __forceinline__ unsigned f2tf(float f) {
    unsigned r;
    asm("cvt.rna.tf32.f32 %0, %1;" : "=r"(r) : "f"(f));
    return r;
}
__device__ __forceinline__ void mma_tf32(float c[4], unsigned a0, unsigned a1,
                                         unsigned a2, unsigned a3,
                                         unsigned b0, unsigned b1) {
    asm volatile(
        "mma.sync.aligned.m16n8k8.row.col.f32.tf32.tf32.f32 "
        "{%0,%1,%2,%3}, {%4,%5,%6,%7}, {%8,%9}, {%0,%1,%2,%3};"
        : "+f"(c[0]), "+f"(c[1]), "+f"(c[2]), "+f"(c[3])
        : "r"(a0), "r"(a1), "r"(a2), "r"(a3), "r"(b0), "r"(b1));
}
__device__ __forceinline__ void cpa16(unsigned saddr, const void* g) {
    asm volatile("cp.async.cg.shared.global [%0], [%1], 16;" :: "r"(saddr), "l"(g));
}
__device__ __forceinline__ void cpa_commit() {
    asm volatile("cp.async.commit_group;");
}

// ---------------------------------------------------------------------------
// fp32 -> tf32 pre-conversion (3 big inputs / 4 weights)
// ---------------------------------------------------------------------------
__global__ void cvt3_kernel(const float* __restrict__ a, const float* __restrict__ b,
                            const float* __restrict__ c, unsigned* __restrict__ oa,
                            unsigned* __restrict__ ob, unsigned* __restrict__ oc) {
    const float* s = (blockIdx.y == 0) ? a : (blockIdx.y == 1) ? b : c;
    unsigned* d    = (blockIdx.y == 0) ? oa : (blockIdx.y == 1) ? ob : oc;
    const int i = (blockIdx.x * 256 + threadIdx.x) * 4;
    float4 v = *(const float4*)(s + i);
    *(uint4*)(d + i) = make_uint4(f2tf(v.x), f2tf(v.y), f2tf(v.z), f2tf(v.w));
}
__global__ void cvtW_kernel(const float* __restrict__ w0, const float* __restrict__ w1,
                            const float* __restrict__ w2, const float* __restrict__ w3,
                            unsigned* __restrict__ dst) {
    const float* s = (blockIdx.y == 0) ? w0 : (blockIdx.y == 1) ? w1
                     : (blockIdx.y == 2) ? w2 : w3;
    unsigned* d = dst + (size_t)blockIdx.y * WELEM;
    const int i = (blockIdx.x * 256 + threadIdx.x) * 4;
    float4 v = *(const float4*)(s + i);
    *(uint4*)(d + i) = make_uint4(f2tf(v.x), f2tf(v.y), f2tf(v.z), f2tf(v.w));
}

// ---------------------------------------------------------------------------
// TF32 SGEMM v2: C[4096,1024] = A @ W + bias (+ physics), A/W pre-tf32.
// 128x128x32 CTA tile, 2-stage cp.async pipeline, 8 warps (2m x 4n).
// As[m][k] stride 36; Bs[k][n] stride 136 (conflict-free, proven in R2/R4).
// out_tf32: write u32 tf32 (with oscale) else fp32.
// ---------------------------------------------------------------------------
#define GEMM_AS_STG 4608            // 128*36
#define GEMM_BS_STG 4352            // 32*136
#define GEMM_SMEM_BYTES ((GEMM_AS_STG + GEMM_BS_STG) * 2 * 4)  // 71680

__global__ __launch_bounds__(256, 2)
void sgemm_tf32_v2(const unsigned* __restrict__ A, const unsigned* __restrict__ W,
                   const float* __restrict__ bias, void* __restrict__ Cout,
                   int out_tf32, float oscale,
                   const float* __restrict__ phys, const float* __restrict__ Pw,
                   const float* __restrict__ pb) {
    extern __shared__ unsigned sg[];
    unsigned* As = sg;                       // [2][4608]
    unsigned* Bs = sg + 2 * GEMM_AS_STG;     // [2][4352]
    const unsigned sA = (unsigned)__cvta_generic_to_shared(As);
    const unsigned sB = (unsigned)__cvta_generic_to_shared(Bs);

    const int t    = threadIdx.x;
    const int w    = t >> 5;
    const int lane = t & 31;
    const int wm   = w >> 2;
    const int wn   = w & 3;
    const int gr   = lane >> 2;
    const int gc   = lane & 3;
    const int n0   = blockIdx.x * 128;
    const int m0   = blockIdx.y * 128;

    float c[4][4][4];
#pragma unroll
    for (int mi = 0; mi < 4; mi++)
#pragma unroll
        for (int ni = 0; ni < 4; ni++)
#pragma unroll
            for (int r = 0; r < 4; r++) c[mi][ni][r] = 0.f;

    // cp.async issue for one stage: A 128x32 (1024 chunks), B 32x128 (1024 chunks)
    auto issue = [&](int stage, int k0) {
#pragma unroll
        for (int i = 0; i < 4; i++) {
            const int ca = t + i * 256;
            const int ar = ca >> 3, ac = (ca & 7) * 4;
            cpa16(sA + (stage * GEMM_AS_STG + ar * 36 + ac) * 4,
                  A + (size_t)(m0 + ar) * DIM + k0 + ac);
            const int br = ca >> 5, bc = (ca & 31) * 4;
            cpa16(sB + (stage * GEMM_BS_STG + br * 136 + bc) * 4,
                  W + (size_t)(k0 + br) * DIM + n0 + bc);
        }
        cpa_commit();
    };

    issue(0, 0);

    for (int it = 0; it < 32; it++) {
        if (it < 31) issue((it + 1) & 1, (it + 1) * 32);
        if (it < 31) asm volatile("cp.async.wait_group 1;");
        else         asm volatile("cp.async.wait_group 0;");
        __syncthreads();

        const unsigned* Asb = As + (it & 1) * GEMM_AS_STG;
        const unsigned* Bsb = Bs + (it & 1) * GEMM_BS_STG;
#pragma unroll
        for (int ks = 0; ks < 4; ks++) {
            unsigned a[4][4];
#pragma unroll
            for (int mi = 0; mi < 4; mi++) {
                const int mr = wm * 64 + mi * 16 + gr;
                a[mi][0] = Asb[mr * 36 + ks * 8 + gc];
                a[mi][1] = Asb[(mr + 8) * 36 + ks * 8 + gc];
                a[mi][2] = Asb[mr * 36 + ks * 8 + gc + 4];
                a[mi][3] = Asb[(mr + 8) * 36 + ks * 8 + gc + 4];
            }
            unsigned b[4][2];
#pragma unroll
            for (int ni = 0; ni < 4; ni++) {
                const int nc = wn * 32 + ni * 8 + gr;
                b[ni][0] = Bsb[(ks * 8 + gc) * 136 + nc];
                b[ni][1] = Bsb[(ks * 8 + gc + 4) * 136 + nc];
            }
#pragma unroll
            for (int mi = 0; mi < 4; mi++)
#pragma unroll
                for (int ni = 0; ni < 4; ni++)
                    mma_tf32(c[mi][ni], a[mi][0], a[mi][1], a[mi][2], a[mi][3],
                             b[ni][0], b[ni][1]);
        }
        __syncthreads();
    }

    // Epilogue
    const float pbv = phys ? pb[0] : 0.f;
#pragma unroll
    for (int mi = 0; mi < 4; mi++) {
#pragma unroll
        for (int h2 = 0; h2 < 2; h2++) {
            const int m = m0 + wm * 64 + mi * 16 + gr + h2 * 8;
            float p0 = 0.f, p1 = 0.f, p2 = 0.f;
            int jjb = 0;
            if (phys) {
                const int bi = m >> 11;
                const int s  = m & 2047;
                const float* ph = phys + (size_t)((bi << 7) + (s >> 4)) * 3;
                p0 = ph[0]; p1 = ph[1]; p2 = ph[2];
                jjb = (s & 15) << 6;
            }
#pragma unroll
            for (int ni = 0; ni < 4; ni++) {
                const int n = n0 + wn * 32 + ni * 8 + 2 * gc;
                float v0 = c[mi][ni][h2 * 2 + 0] + bias[n];
                float v1 = c[mi][ni][h2 * 2 + 1] + bias[n + 1];
                if (phys) {
                    const int j0 = jjb + (n & 63);
                    v0 += pbv * (p0 * Pw[j0]     + p1 * Pw[1024 + j0]     + p2 * Pw[2048 + j0]);
                    v1 += pbv * (p0 * Pw[j0 + 1] + p1 * Pw[1024 + j0 + 1] + p2 * Pw[2048 + j0 + 1]);
                }
                if (out_tf32) {
                    *(uint2*)&((unsigned*)Cout)[(size_t)m * DIM + n] =
                        make_uint2(f2tf(v0 * oscale), f2tf(v1 * oscale));
                } else {
                    *(float2*)&((float*)Cout)[(size_t)m * DIM + n] = make_float2(v0, v1);
                }
            }
        }
    }
}

// ---------------------------------------------------------------------------
// Flash attention v2: all inputs pre-tf32 (Q pre-scaled by 0.125), cp.async
// staging, K-tile prefetch under softmax+GEMM2. Output ctx written as tf32.
// SMEM (u32): Qs[128][68] | Ks[64][68] | Vs[64][72] | Ps[128][68]
// ---------------------------------------------------------------------------
#define QS_OFF 0
#define KS_OFF 8704
#define VS_OFF 13056
#define PS_OFF 17664
#define ATTN_SMEM_BYTES ((17664 + 128 * 68) * 4)   // 105472

__global__ __launch_bounds__(256, 2)
void attn_tf32_v2(const unsigned* __restrict__ Q, const unsigned* __restrict__ K,
                  const unsigned* __restrict__ V, unsigned* __restrict__ O) {
    extern __shared__ unsigned sm_u[];
    unsigned* Qs = sm_u + QS_OFF;
    unsigned* Ks = sm_u + KS_OFF;
    unsigned* Vs = sm_u + VS_OFF;
    unsigned* Ps = sm_u + PS_OFF;
    const unsigned sQ = (unsigned)__cvta_generic_to_shared(Qs);
    const unsigned sK = (unsigned)__cvta_generic_to_shared(Ks);
    const unsigned sV = (unsigned)__cvta_generic_to_shared(Vs);

    const int t    = threadIdx.x;
    const int w    = t >> 5;
    const int lane = t & 31;
    const int gr   = lane >> 2;
    const int gc   = lane & 3;
    const int qw   = w * 16;
    const int qb   = blockIdx.x;
    const int h    = blockIdx.y;
    const int b    = blockIdx.z;
    const int q0   = qb * 128;

    const unsigned* Qg = Q + ((size_t)(b * SEQ + q0)) * DIM + h * DKH;
    const unsigned* Kg = K + ((size_t)b * SEQ) * DIM + h * DKH;
    const unsigned* Vg = V + ((size_t)b * SEQ) * DIM + h * DKH;

    // Q tile -> smem: 128 rows x 64 cols = 2048 float4 chunks (8 per thread)
#pragma unroll
    for (int i = 0; i < 8; i++) {
        const int cq = t + i * 256;            // 0..2047
        const int r = cq >> 4, d = (cq & 15) * 4;
        cpa16(sQ + (r * 68 + d) * 4, Qg + (size_t)r * DIM + d);
    }
    cpa_commit();

    auto issueK = [&](int kt) {
#pragma unroll
        for (int i = 0; i < 4; i++) {
            const int cc = t + i * 256;        // 1024 chunks (64 rows x 16)
            const int r = cc >> 4, d = (cc & 15) * 4;
            cpa16(sK + (r * 68 + d) * 4, Kg + (size_t)(kt * 64 + r) * DIM + d);
        }
        cpa_commit();
    };
    auto issueV = [&](int kt) {
#pragma unroll
        for (int i = 0; i < 4; i++) {
            const int cc = t + i * 256;
            const int r = cc >> 4, d = (cc & 15) * 4;
            cpa16(sV + (r * 72 + d) * 4, Vg + (size_t)(kt * 64 + r) * DIM + d);
        }
        cpa_commit();
    };

    issueK(0);
    issueV(0);

    float m0 = -1e30f, m1 = -1e30f, l0 = 0.f, l1 = 0.f;
    float o[8][4];
#pragma unroll
    for (int di = 0; di < 8; di++)
#pragma unroll
        for (int r = 0; r < 4; r++) o[di][r] = 0.f;

    for (int kt = 0; kt < SEQ / 64; kt++) {
        asm volatile("cp.async.wait_group 0;");
        __syncthreads();

        // GEMM1: S[16q x 64k]
        float s[8][4];
#pragma unroll
        for (int ni = 0; ni < 8; ni++)
#pragma unroll
            for (int r = 0; r < 4; r++) s[ni][r] = 0.f;
#pragma unroll
        for (int ks = 0; ks < 8; ks++) {
            const unsigned a0 = Qs[(qw + gr) * 68 + ks * 8 + gc];
            const unsigned a1 = Qs[(qw + gr + 8) * 68 + ks * 8 + gc];
            const unsigned a2 = Qs[(qw + gr) * 68 + ks * 8 + gc + 4];
            const unsigned a3 = Qs[(qw + gr + 8) * 68 + ks * 8 + gc + 4];
#pragma unroll
            for (int ni = 0; ni < 8; ni++) {
                const unsigned b0 = Ks[(ni * 8 + gr) * 68 + ks * 8 + gc];
                const unsigned b1 = Ks[(ni * 8 + gr) * 68 + ks * 8 + gc + 4];
                mma_tf32(s[ni], a0, a1, a2, a3, b0, b1);
            }
        }
        __syncthreads();                 // everyone done reading Ks
        if (kt + 1 < SEQ / 64) issueK(kt + 1);   // prefetch next K under softmax/GEMM2

        // Online softmax (Q pre-scaled by 1/8, so s is already the score)
        float mx0 = -1e30f, mx1 = -1e30f;
#pragma unroll
        for (int ni = 0; ni < 8; ni++) {
            mx0 = fmaxf(mx0, fmaxf(s[ni][0], s[ni][1]));
            mx1 = fmaxf(mx1, fmaxf(s[ni][2], s[ni][3]));
        }
        mx0 = fmaxf(mx0, __shfl_xor_sync(0xffffffffu, mx0, 1));
        mx0 = fmaxf(mx0, __shfl_xor_sync(0xffffffffu, mx0, 2));
        mx1 = fmaxf(mx1, __shfl_xor_sync(0xffffffffu, mx1, 1));
        mx1 = fmaxf(mx1, __shfl_xor_sync(0xffffffffu, mx1, 2));
        const float mn0 = fmaxf(m0, mx0), mn1 = fmaxf(m1, mx1);
        const float al0 = __expf(m0 - mn0), al1 = __expf(m1 - mn1);
        m0 = mn0; m1 = mn1;
        float rs0 = 0.f, rs1 = 0.f;
#pragma unroll
        for (int ni = 0; ni < 8; ni++) {
            s[ni][0] = __expf(s[ni][0] - mn0);
            s[ni][1] = __expf(s[ni][1] - mn0);
            s[ni][2] = __expf(s[ni][2] - mn1);
            s[ni][3] = __expf(s[ni][3] - mn1);
            rs0 += s[ni][0] + s[ni][1];
            rs1 += s[ni][2] + s[ni][3];
        }
        rs0 += __shfl_xor_sync(0xffffffffu, rs0, 1);
        rs0 += __shfl_xor_sync(0xffffffffu, rs0, 2);
        rs1 += __shfl_xor_sync(0xffffffffu, rs1, 1);
        rs1 += __shfl_xor_sync(0xffffffffu, rs1, 2);
        l0 = l0 * al0 + rs0;
        l1 = l1 * al1 + rs1;

        // P -> warp-private smem rows (tf32)
#pragma unroll
        for (int ni = 0; ni < 8; ni++) {
            *(uint2*)&Ps[(qw + gr) * 68 + ni * 8 + 2 * gc] =
                make_uint2(f2tf(s[ni][0]), f2tf(s[ni][1]));
            *(uint2*)&Ps[(qw + gr + 8) * 68 + ni * 8 + 2 * gc] =
                make_uint2(f2tf(s[ni][2]), f2tf(s[ni][3]));
        }
#pragma unroll
        for (int di = 0; di < 8; di++) {
            o[di][0] *= al0; o[di][1] *= al0;
            o[di][2] *= al1; o[di][3] *= al1;
        }
        __syncwarp();

        // GEMM2: O += P @ V
#pragma unroll
        for (int ks = 0; ks < 8; ks++) {
            const unsigned a0 = Ps[(qw + gr) * 68 + ks * 8 + gc];
            const unsigned a1 = Ps[(qw + gr + 8) * 68 + ks * 8 + gc];
            const unsigned a2 = Ps[(qw + gr) * 68 + ks * 8 + gc + 4];
            const unsigned a3 = Ps[(qw + gr + 8) * 68 + ks * 8 + gc + 4];
#pragma unroll
            for (int di = 0; di < 8; di++) {
                const unsigned b0 = Vs[(ks * 8 + gc) * 72 + di * 8 + gr];
                const unsigned b1 = Vs[(ks * 8 + gc + 4) * 72 + di * 8 + gr];
                mma_tf32(o[di], a0, a1, a2, a3, b0, b1);
            }
        }
        __syncthreads();                 // everyone done reading Vs
        if (kt + 1 < SEQ / 64) issueV(kt + 1);
    }

    // Epilogue: normalize, store ctx as tf32
    const float i0 = 1.f / l0, i1 = 1.f / l1;
    const size_t r0 = (size_t)(b * SEQ + q0 + qw + gr) * DIM + h * DKH;
    const size_t r1 = (size_t)(b * SEQ + q0 + qw + gr + 8) * DIM + h * DKH;
#pragma unroll
    for (int di = 0; di < 8; di++) {
        const int col = di * 8 + 2 * gc;
        *(uint2*)&O[r0 + col] = make_uint2(f2tf(o[di][0] * i0), f2tf(o[di][1] * i0));
        *(uint2*)&O[r1 + col] = make_uint2(f2tf(o[di][2] * i1), f2tf(o[di][3] * i1));
    }
}

// ---------------------------------------------------------------------------
// Launch
// ---------------------------------------------------------------------------
extern "C" void kernel_launch(void* const* d_in, const int* in_sizes, int n_in,
                              void* d_out, int out_size) {
    const float* query  = (const float*)d_in[0];
    const float* key_in = (const float*)d_in[1];
    const float* value  = (const float*)d_in[2];
    const float* phys   = (const float*)d_in[3];
    const float* Wq     = (const float*)d_in[4];
    const float* bq     = (const float*)d_in[5];
    const float* Wk     = (const float*)d_in[6];
    const float* bk     = (const float*)d_in[7];
    const float* Wv     = (const float*)d_in[8];
    const float* bv     = (const float*)d_in[9];
    const float* Wo     = (const float*)d_in[10];
    const float* bo     = (const float*)d_in[11];
    const float* Pw     = (const float*)d_in[12];
    const float* pb     = (const float*)d_in[13];
    float* out          = (float*)d_out;

    unsigned *pQ, *pK, *pV, *pC, *tA0, *tA1, *tA2, *tW;
    cudaGetSymbolAddress((void**)&pQ,  g_Q);
    cudaGetSymbolAddress((void**)&pK,  g_K);
    cudaGetSymbolAddress((void**)&pV,  g_V);
    cudaGetSymbolAddress((void**)&pC,  g_ctx);
    cudaGetSymbolAddress((void**)&tA0, g_tA0);
    cudaGetSymbolAddress((void**)&tA1, g_tA1);
    cudaGetSymbolAddress((void**)&tA2, g_tA2);
    cudaGetSymbolAddress((void**)&tW,  g_tW);

    cudaFuncSetAttribute(sgemm_tf32_v2, cudaFuncAttributeMaxDynamicSharedMemorySize,
                         GEMM_SMEM_BYTES);
    cudaFuncSetAttribute(attn_tf32_v2, cudaFuncAttributeMaxDynamicSharedMemorySize,
                         ATTN_SMEM_BYTES);

    // Pre-convert inputs and weights to tf32
    cvt3_kernel<<<dim3(NELEM / 1024, 3), 256>>>(query, key_in, value, tA0, tA1, tA2);
    cvtW_kernel<<<dim3(WELEM / 1024, 4), 256>>>(Wq, Wk, Wv, Wo, tW);

    dim3 gg(DIM / 128, MROWS / 128);   // (8, 32)
    // Q projection: fold 1/sqrt(DK)=0.125 into output
    sgemm_tf32_v2<<<gg, 256, GEMM_SMEM_BYTES>>>(tA0, tW + 0 * WELEM, bq, pQ, 1, 0.125f,
                                                nullptr, nullptr, nullptr);
    // K projection with physics fold
    sgemm_tf32_v2<<<gg, 256, GEMM_SMEM_BYTES>>>(tA1, tW + 1 * WELEM, bk, pK, 1, 1.0f,
                                                phys, Pw, pb);
    // V projection
    sgemm_tf32_v2<<<gg, 256, GEMM_SMEM_BYTES>>>(tA2, tW + 2 * WELEM, bv, pV, 1, 1.0f,
                                                nullptr, nullptr, nullptr);
    // Attention
    dim3 ga(SEQ / 128, HEADS, 2);      // (16, 16, 2)
    attn_tf32_v2<<<ga, 256, ATTN_SMEM_BYTES>>>(pQ, pK, pV, pC);
    // Output projection (fp32 out)
    sgemm_tf32_v2<<<gg, 256, GEMM_SMEM_BYTES>>>(pC, tW + 3 * WELEM, bo, out, 0, 1.0f,
                                                nullptr, nullptr, nullptr);
}

// round 8
// speedup vs baseline: 6.3622x; 1.0008x over previous
#include <cuda_runtime.h>
#include <cuda_bf16.h>
#include <cstdint>

#define MROWS 4096
#define DIM   1024
#define HEADS 16
#define DKH   64
#define SEQ   2048
#define NELEM (MROWS * DIM)
#define WELEM (DIM * DIM)

// ---------------------------------------------------------------------------
// Scratch (device globals; no allocation allowed). All tf32 payloads as u32.
// ---------------------------------------------------------------------------
__device__ unsigned g_Q[NELEM];
__device__ unsigned g_K[NELEM];
__device__ unsigned g_V[NELEM];
__device__ unsigned g_ctx[NELEM];
__device__ unsigned g_tA0[NELEM];    // query  (tf32)
__device__ unsigned g_tA1[NELEM];    // key_in (tf32)
__device__ unsigned g_tA2[NELEM];    // value  (tf32)
__device__ unsigned g_tW[4 * WELEM]; // Wq,Wk,Wv,Wo (tf32)

// ---------------------------------------------------------------------------
// Helpers
// ---------------------------------------------------------------------------
__device__ __forceinline__ unsigned f2tf(float f) {
    unsigned r;
    asm("cvt.rna.tf32.f32 %0, %1;" : "=r"(r) : "f"(f));
    return r;
}
__device__ __forceinline__ void mma_tf32(float c[4], unsigned a0, unsigned a1,
                                         unsigned a2, unsigned a3,
                                         unsigned b0, unsigned b1) {
    asm volatile(
        "mma.sync.aligned.m16n8k8.row.col.f32.tf32.tf32.f32 "
        "{%0,%1,%2,%3}, {%4,%5,%6,%7}, {%8,%9}, {%0,%1,%2,%3};"
        : "+f"(c[0]), "+f"(c[1]), "+f"(c[2]), "+f"(c[3])
        : "r"(a0), "r"(a1), "r"(a2), "r"(a3), "r"(b0), "r"(b1));
}
__device__ __forceinline__ void cpa16(unsigned saddr, const void* g) {
    asm volatile("cp.async.cg.shared.global [%0], [%1], 16;" :: "r"(saddr), "l"(g));
}
__device__ __forceinline__ void cpa_commit() {
    asm volatile("cp.async.commit_group;");
}

// ---------------------------------------------------------------------------
// fp32 -> tf32 pre-conversion (3 big inputs / 4 weights)
// ---------------------------------------------------------------------------
__global__ void cvt3_kernel(const float* __restrict__ a, const float* __restrict__ b,
                            const float* __restrict__ c, unsigned* __restrict__ oa,
                            unsigned* __restrict__ ob, unsigned* __restrict__ oc) {
    const float* s = (blockIdx.y == 0) ? a : (blockIdx.y == 1) ? b : c;
    unsigned* d    = (blockIdx.y == 0) ? oa : (blockIdx.y == 1) ? ob : oc;
    const int i = (blockIdx.x * 256 + threadIdx.x) * 4;
    float4 v = *(const float4*)(s + i);
    *(uint4*)(d + i) = make_uint4(f2tf(v.x), f2tf(v.y), f2tf(v.z), f2tf(v.w));
}
__global__ void cvtW_kernel(const float* __restrict__ w0, const float* __restrict__ w1,
                            const float* __restrict__ w2, const float* __restrict__ w3,
                            unsigned* __restrict__ dst) {
    const float* s = (blockIdx.y == 0) ? w0 : (blockIdx.y == 1) ? w1
                     : (blockIdx.y == 2) ? w2 : w3;
    unsigned* d = dst + (size_t)blockIdx.y * WELEM;
    const int i = (blockIdx.x * 256 + threadIdx.x) * 4;
    float4 v = *(const float4*)(s + i);
    *(uint4*)(d + i) = make_uint4(f2tf(v.x), f2tf(v.y), f2tf(v.z), f2tf(v.w));
}

// ---------------------------------------------------------------------------
// TF32 SGEMM v2: C[4096,1024] = A @ W + bias (+ physics), A/W pre-tf32.
// 128x128x32 CTA tile, 2-stage cp.async pipeline, 8 warps (2m x 4n).
// As[m][k] stride 36; Bs[k][n] stride 136 (conflict-free, proven in R2/R4).
// out_tf32: write u32 tf32 (with oscale) else fp32.
// ---------------------------------------------------------------------------
#define GEMM_AS_STG 4608            // 128*36
#define GEMM_BS_STG 4352            // 32*136
#define GEMM_SMEM_BYTES ((GEMM_AS_STG + GEMM_BS_STG) * 2 * 4)  // 71680

__global__ __launch_bounds__(256, 2)
void sgemm_tf32_v2(const unsigned* __restrict__ A, const unsigned* __restrict__ W,
                   const float* __restrict__ bias, void* __restrict__ Cout,
                   int out_tf32, float oscale,
                   const float* __restrict__ phys, const float* __restrict__ Pw,
                   const float* __restrict__ pb) {
    extern __shared__ unsigned sg[];
    unsigned* As = sg;                       // [2][4608]
    unsigned* Bs = sg + 2 * GEMM_AS_STG;     // [2][4352]
    const unsigned sA = (unsigned)__cvta_generic_to_shared(As);
    const unsigned sB = (unsigned)__cvta_generic_to_shared(Bs);

    const int t    = threadIdx.x;
    const int w    = t >> 5;
    const int lane = t & 31;
    const int wm   = w >> 2;
    const int wn   = w & 3;
    const int gr   = lane >> 2;
    const int gc   = lane & 3;
    const int n0   = blockIdx.x * 128;
    const int m0   = blockIdx.y * 128;

    float c[4][4][4];
#pragma unroll
    for (int mi = 0; mi < 4; mi++)
#pragma unroll
        for (int ni = 0; ni < 4; ni++)
#pragma unroll
            for (int r = 0; r < 4; r++) c[mi][ni][r] = 0.f;

    // cp.async issue for one stage: A 128x32 (1024 chunks), B 32x128 (1024 chunks)
    auto issue = [&](int stage, int k0) {
#pragma unroll
        for (int i = 0; i < 4; i++) {
            const int ca = t + i * 256;
            const int ar = ca >> 3, ac = (ca & 7) * 4;
            cpa16(sA + (stage * GEMM_AS_STG + ar * 36 + ac) * 4,
                  A + (size_t)(m0 + ar) * DIM + k0 + ac);
            const int br = ca >> 5, bc = (ca & 31) * 4;
            cpa16(sB + (stage * GEMM_BS_STG + br * 136 + bc) * 4,
                  W + (size_t)(k0 + br) * DIM + n0 + bc);
        }
        cpa_commit();
    };

    issue(0, 0);

    for (int it = 0; it < 32; it++) {
        if (it < 31) issue((it + 1) & 1, (it + 1) * 32);
        if (it < 31) asm volatile("cp.async.wait_group 1;");
        else         asm volatile("cp.async.wait_group 0;");
        __syncthreads();

        const unsigned* Asb = As + (it & 1) * GEMM_AS_STG;
        const unsigned* Bsb = Bs + (it & 1) * GEMM_BS_STG;
#pragma unroll
        for (int ks = 0; ks < 4; ks++) {
            unsigned a[4][4];
#pragma unroll
            for (int mi = 0; mi < 4; mi++) {
                const int mr = wm * 64 + mi * 16 + gr;
                a[mi][0] = Asb[mr * 36 + ks * 8 + gc];
                a[mi][1] = Asb[(mr + 8) * 36 + ks * 8 + gc];
                a[mi][2] = Asb[mr * 36 + ks * 8 + gc + 4];
                a[mi][3] = Asb[(mr + 8) * 36 + ks * 8 + gc + 4];
            }
            unsigned b[4][2];
#pragma unroll
            for (int ni = 0; ni < 4; ni++) {
                const int nc = wn * 32 + ni * 8 + gr;
                b[ni][0] = Bsb[(ks * 8 + gc) * 136 + nc];
                b[ni][1] = Bsb[(ks * 8 + gc + 4) * 136 + nc];
            }
#pragma unroll
            for (int mi = 0; mi < 4; mi++)
#pragma unroll
                for (int ni = 0; ni < 4; ni++)
                    mma_tf32(c[mi][ni], a[mi][0], a[mi][1], a[mi][2], a[mi][3],
                             b[ni][0], b[ni][1]);
        }
        __syncthreads();
    }

    // Epilogue
    const float pbv = phys ? pb[0] : 0.f;
#pragma unroll
    for (int mi = 0; mi < 4; mi++) {
#pragma unroll
        for (int h2 = 0; h2 < 2; h2++) {
            const int m = m0 + wm * 64 + mi * 16 + gr + h2 * 8;
            float p0 = 0.f, p1 = 0.f, p2 = 0.f;
            int jjb = 0;
            if (phys) {
                const int bi = m >> 11;
                const int s  = m & 2047;
                const float* ph = phys + (size_t)((bi << 7) + (s >> 4)) * 3;
                p0 = ph[0]; p1 = ph[1]; p2 = ph[2];
                jjb = (s & 15) << 6;
            }
#pragma unroll
            for (int ni = 0; ni < 4; ni++) {
                const int n = n0 + wn * 32 + ni * 8 + 2 * gc;
                float v0 = c[mi][ni][h2 * 2 + 0] + bias[n];
                float v1 = c[mi][ni][h2 * 2 + 1] + bias[n + 1];
                if (phys) {
                    const int j0 = jjb + (n & 63);
                    v0 += pbv * (p0 * Pw[j0]     + p1 * Pw[1024 + j0]     + p2 * Pw[2048 + j0]);
                    v1 += pbv * (p0 * Pw[j0 + 1] + p1 * Pw[1024 + j0 + 1] + p2 * Pw[2048 + j0 + 1]);
                }
                if (out_tf32) {
                    *(uint2*)&((unsigned*)Cout)[(size_t)m * DIM + n] =
                        make_uint2(f2tf(v0 * oscale), f2tf(v1 * oscale));
                } else {
                    *(float2*)&((float*)Cout)[(size_t)m * DIM + n] = make_float2(v0, v1);
                }
            }
        }
    }
}

// ---------------------------------------------------------------------------
// Flash attention v2: all inputs pre-tf32 (Q pre-scaled by 0.125), cp.async
// staging, K-tile prefetch under softmax+GEMM2. Output ctx written as tf32.
// SMEM (u32): Qs[128][68] | Ks[64][68] | Vs[64][72] | Ps[128][68]
// ---------------------------------------------------------------------------
#define QS_OFF 0
#define KS_OFF 8704
#define VS_OFF 13056
#define PS_OFF 17664
#define ATTN_SMEM_BYTES ((17664 + 128 * 68) * 4)   // 105472

__global__ __launch_bounds__(256, 2)
void attn_tf32_v2(const unsigned* __restrict__ Q, const unsigned* __restrict__ K,
                  const unsigned* __restrict__ V, unsigned* __restrict__ O) {
    extern __shared__ unsigned sm_u[];
    unsigned* Qs = sm_u + QS_OFF;
    unsigned* Ks = sm_u + KS_OFF;
    unsigned* Vs = sm_u + VS_OFF;
    unsigned* Ps = sm_u + PS_OFF;
    const unsigned sQ = (unsigned)__cvta_generic_to_shared(Qs);
    const unsigned sK = (unsigned)__cvta_generic_to_shared(Ks);
    const unsigned sV = (unsigned)__cvta_generic_to_shared(Vs);

    const int t    = threadIdx.x;
    const int w    = t >> 5;
    const int lane = t & 31;
    const int gr   = lane >> 2;
    const int gc   = lane & 3;
    const int qw   = w * 16;
    const int qb   = blockIdx.x;
    const int h    = blockIdx.y;
    const int b    = blockIdx.z;
    const int q0   = qb * 128;

    const unsigned* Qg = Q + ((size_t)(b * SEQ + q0)) * DIM + h * DKH;
    const unsigned* Kg = K + ((size_t)b * SEQ) * DIM + h * DKH;
    const unsigned* Vg = V + ((size_t)b * SEQ) * DIM + h * DKH;

    // Q tile -> smem: 128 rows x 64 cols = 2048 float4 chunks (8 per thread)
#pragma unroll
    for (int i = 0; i < 8; i++) {
        const int cq = t + i * 256;            // 0..2047
        const int r = cq >> 4, d = (cq & 15) * 4;
        cpa16(sQ + (r * 68 + d) * 4, Qg + (size_t)r * DIM + d);
    }
    cpa_commit();

    auto issueK = [&](int kt) {
#pragma unroll
        for (int i = 0; i < 4; i++) {
            const int cc = t + i * 256;        // 1024 chunks (64 rows x 16)
            const int r = cc >> 4, d = (cc & 15) * 4;
            cpa16(sK + (r * 68 + d) * 4, Kg + (size_t)(kt * 64 + r) * DIM + d);
        }
        cpa_commit();
    };
    auto issueV = [&](int kt) {
#pragma unroll
        for (int i = 0; i < 4; i++) {
            const int cc = t + i * 256;
            const int r = cc >> 4, d = (cc & 15) * 4;
            cpa16(sV + (r * 72 + d) * 4, Vg + (size_t)(kt * 64 + r) * DIM + d);
        }
        cpa_commit();
    };

    issueK(0);
    issueV(0);

    float m0 = -1e30f, m1 = -1e30f, l0 = 0.f, l1 = 0.f;
    float o[8][4];
#pragma unroll
    for (int di = 0; di < 8; di++)
#pragma unroll
        for (int r = 0; r < 4; r++) o[di][r] = 0.f;

    for (int kt = 0; kt < SEQ / 64; kt++) {
        asm volatile("cp.async.wait_group 0;");
        __syncthreads();

        // GEMM1: S[16q x 64k]
        float s[8][4];
#pragma unroll
        for (int ni = 0; ni < 8; ni++)
#pragma unroll
            for (int r = 0; r < 4; r++) s[ni][r] = 0.f;
#pragma unroll
        for (int ks = 0; ks < 8; ks++) {
            const unsigned a0 = Qs[(qw + gr) * 68 + ks * 8 + gc];
            const unsigned a1 = Qs[(qw + gr + 8) * 68 + ks * 8 + gc];
            const unsigned a2 = Qs[(qw + gr) * 68 + ks * 8 + gc + 4];
            const unsigned a3 = Qs[(qw + gr + 8) * 68 + ks * 8 + gc + 4];
#pragma unroll
            for (int ni = 0; ni < 8; ni++) {
                const unsigned b0 = Ks[(ni * 8 + gr) * 68 + ks * 8 + gc];
                const unsigned b1 = Ks[(ni * 8 + gr) * 68 + ks * 8 + gc + 4];
                mma_tf32(s[ni], a0, a1, a2, a3, b0, b1);
            }
        }
        __syncthreads();                 // everyone done reading Ks
        if (kt + 1 < SEQ / 64) issueK(kt + 1);   // prefetch next K under softmax/GEMM2

        // Online softmax (Q pre-scaled by 1/8, so s is already the score)
        float mx0 = -1e30f, mx1 = -1e30f;
#pragma unroll
        for (int ni = 0; ni < 8; ni++) {
            mx0 = fmaxf(mx0, fmaxf(s[ni][0], s[ni][1]));
            mx1 = fmaxf(mx1, fmaxf(s[ni][2], s[ni][3]));
        }
        mx0 = fmaxf(mx0, __shfl_xor_sync(0xffffffffu, mx0, 1));
        mx0 = fmaxf(mx0, __shfl_xor_sync(0xffffffffu, mx0, 2));
        mx1 = fmaxf(mx1, __shfl_xor_sync(0xffffffffu, mx1, 1));
        mx1 = fmaxf(mx1, __shfl_xor_sync(0xffffffffu, mx1, 2));
        const float mn0 = fmaxf(m0, mx0), mn1 = fmaxf(m1, mx1);
        const float al0 = __expf(m0 - mn0), al1 = __expf(m1 - mn1);
        m0 = mn0; m1 = mn1;
        float rs0 = 0.f, rs1 = 0.f;
#pragma unroll
        for (int ni = 0; ni < 8; ni++) {
            s[ni][0] = __expf(s[ni][0] - mn0);
            s[ni][1] = __expf(s[ni][1] - mn0);
            s[ni][2] = __expf(s[ni][2] - mn1);
            s[ni][3] = __expf(s[ni][3] - mn1);
            rs0 += s[ni][0] + s[ni][1];
            rs1 += s[ni][2] + s[ni][3];
        }
        rs0 += __shfl_xor_sync(0xffffffffu, rs0, 1);
        rs0 += __shfl_xor_sync(0xffffffffu, rs0, 2);
        rs1 += __shfl_xor_sync(0xffffffffu, rs1, 1);
        rs1 += __shfl_xor_sync(0xffffffffu, rs1, 2);
        l0 = l0 * al0 + rs0;
        l1 = l1 * al1 + rs1;

        // P -> warp-private smem rows (tf32)
#pragma unroll
        for (int ni = 0; ni < 8; ni++) {
            *(uint2*)&Ps[(qw + gr) * 68 + ni * 8 + 2 * gc] =
                make_uint2(f2tf(s[ni][0]), f2tf(s[ni][1]));
            *(uint2*)&Ps[(qw + gr + 8) * 68 + ni * 8 + 2 * gc] =
                make_uint2(f2tf(s[ni][2]), f2tf(s[ni][3]));
        }
#pragma unroll
        for (int di = 0; di < 8; di++) {
            o[di][0] *= al0; o[di][1] *= al0;
            o[di][2] *= al1; o[di][3] *= al1;
        }
        __syncwarp();

        // GEMM2: O += P @ V
#pragma unroll
        for (int ks = 0; ks < 8; ks++) {
            const unsigned a0 = Ps[(qw + gr) * 68 + ks * 8 + gc];
            const unsigned a1 = Ps[(qw + gr + 8) * 68 + ks * 8 + gc];
            const unsigned a2 = Ps[(qw + gr) * 68 + ks * 8 + gc + 4];
            const unsigned a3 = Ps[(qw + gr + 8) * 68 + ks * 8 + gc + 4];
#pragma unroll
            for (int di = 0; di < 8; di++) {
                const unsigned b0 = Vs[(ks * 8 + gc) * 72 + di * 8 + gr];
                const unsigned b1 = Vs[(ks * 8 + gc + 4) * 72 + di * 8 + gr];
                mma_tf32(o[di], a0, a1, a2, a3, b0, b1);
            }
        }
        __syncthreads();                 // everyone done reading Vs
        if (kt + 1 < SEQ / 64) issueV(kt + 1);
    }

    // Epilogue: normalize, store ctx as tf32
    const float i0 = 1.f / l0, i1 = 1.f / l1;
    const size_t r0 = (size_t)(b * SEQ + q0 + qw + gr) * DIM + h * DKH;
    const size_t r1 = (size_t)(b * SEQ + q0 + qw + gr + 8) * DIM + h * DKH;
#pragma unroll
    for (int di = 0; di < 8; di++) {
        const int col = di * 8 + 2 * gc;
        *(uint2*)&O[r0 + col] = make_uint2(f2tf(o[di][0] * i0), f2tf(o[di][1] * i0));
        *(uint2*)&O[r1 + col] = make_uint2(f2tf(o[di][2] * i1), f2tf(o[di][3] * i1));
    }
}

// ---------------------------------------------------------------------------
// Launch
// ---------------------------------------------------------------------------
extern "C" void kernel_launch(void* const* d_in, const int* in_sizes, int n_in,
                              void* d_out, int out_size) {
    const float* query  = (const float*)d_in[0];
    const float* key_in = (const float*)d_in[1];
    const float* value  = (const float*)d_in[2];
    const float* phys   = (const float*)d_in[3];
    const float* Wq     = (const float*)d_in[4];
    const float* bq     = (const float*)d_in[5];
    const float* Wk     = (const float*)d_in[6];
    const float* bk     = (const float*)d_in[7];
    const float* Wv     = (const float*)d_in[8];
    const float* bv     = (const float*)d_in[9];
    const float* Wo     = (const float*)d_in[10];
    const float* bo     = (const float*)d_in[11];
    const float* Pw     = (const float*)d_in[12];
    const float* pb     = (const float*)d_in[13];
    float* out          = (float*)d_out;

    unsigned *pQ, *pK, *pV, *pC, *tA0, *tA1, *tA2, *tW;
    cudaGetSymbolAddress((void**)&pQ,  g_Q);
    cudaGetSymbolAddress((void**)&pK,  g_K);
    cudaGetSymbolAddress((void**)&pV,  g_V);
    cudaGetSymbolAddress((void**)&pC,  g_ctx);
    cudaGetSymbolAddress((void**)&tA0, g_tA0);
    cudaGetSymbolAddress((void**)&tA1, g_tA1);
    cudaGetSymbolAddress((void**)&tA2, g_tA2);
    cudaGetSymbolAddress((void**)&tW,  g_tW);

    cudaFuncSetAttribute(sgemm_tf32_v2, cudaFuncAttributeMaxDynamicSharedMemorySize,
                         GEMM_SMEM_BYTES);
    cudaFuncSetAttribute(attn_tf32_v2, cudaFuncAttributeMaxDynamicSharedMemorySize,
                         ATTN_SMEM_BYTES);

    // Pre-convert inputs and weights to tf32
    cvt3_kernel<<<dim3(NELEM / 1024, 3), 256>>>(query, key_in, value, tA0, tA1, tA2);
    cvtW_kernel<<<dim3(WELEM / 1024, 4), 256>>>(Wq, Wk, Wv, Wo, tW);

    dim3 gg(DIM / 128, MROWS / 128);   // (8, 32)
    // Q projection: fold 1/sqrt(DK)=0.125 into output
    sgemm_tf32_v2<<<gg, 256, GEMM_SMEM_BYTES>>>(tA0, tW + 0 * WELEM, bq, pQ, 1, 0.125f,
                                                nullptr, nullptr, nullptr);
    // K projection with physics fold
    sgemm_tf32_v2<<<gg, 256, GEMM_SMEM_BYTES>>>(tA1, tW + 1 * WELEM, bk, pK, 1, 1.0f,
                                                phys, Pw, pb);
    // V projection
    sgemm_tf32_v2<<<gg, 256, GEMM_SMEM_BYTES>>>(tA2, tW + 2 * WELEM, bv, pV, 1, 1.0f,
                                                nullptr, nullptr, nullptr);
    // Attention
    dim3 ga(SEQ / 128, HEADS, 2);      // (16, 16, 2)
    attn_tf32_v2<<<ga, 256, ATTN_SMEM_BYTES>>>(pQ, pK, pV, pC);
    // Output projection (fp32 out)
    sgemm_tf32_v2<<<gg, 256, GEMM_SMEM_BYTES>>>(pC, tW + 3 * WELEM, bo, out, 0, 1.0f,
                                                nullptr, nullptr, nullptr);
}

// round 10
// speedup vs baseline: 6.5258x; 1.0257x over previous
#include <cuda_runtime.h>
#include <cuda_bf16.h>
#include <cstdint>

#define MROWS 4096
#define DIM   1024
#define HEADS 16
#define DKH   64
#define SEQ   2048
#define NELEM (MROWS * DIM)
#define WELEM (DIM * DIM)

// ---------------------------------------------------------------------------
// Scratch (device globals; no allocation allowed). All tf32 payloads as u32.
// ---------------------------------------------------------------------------
__device__ unsigned g_Q[NELEM];
__device__ unsigned g_K[NELEM];
__device__ unsigned g_V[NELEM];
__device__ unsigned g_ctx[NELEM];
__device__ unsigned g_tA0[NELEM];    // query  (tf32)
__device__ unsigned g_tA1[NELEM];    // key_in (tf32)
__device__ unsigned g_tA2[NELEM];    // value  (tf32)
__device__ unsigned g_tW[4 * WELEM]; // Wq,Wk,Wv,Wo (tf32, [K][N] layout)

// ---------------------------------------------------------------------------
// Helpers
// ---------------------------------------------------------------------------
__device__ __forceinline__ unsigned f2tf(float f) {
    unsigned r;
    asm("cvt.rna.tf32.f32 %0, %1;" : "=r"(r) : "f"(f));
    return r;
}
__device__ __forceinline__ void mma_tf32(float c[4], unsigned a0, unsigned a1,
                                         unsigned a2, unsigned a3,
                                         unsigned b0, unsigned b1) {
    asm volatile(
        "mma.sync.aligned.m16n8k8.row.col.f32.tf32.tf32.f32 "
        "{%0,%1,%2,%3}, {%4,%5,%6,%7}, {%8,%9}, {%0,%1,%2,%3};"
        : "+f"(c[0]), "+f"(c[1]), "+f"(c[2]), "+f"(c[3])
        : "r"(a0), "r"(a1), "r"(a2), "r"(a3), "r"(b0), "r"(b1));
}
__device__ __forceinline__ void cpa16(unsigned saddr, const void* g) {
    asm volatile("cp.async.cg.shared.global [%0], [%1], 16;" :: "r"(saddr), "l"(g));
}
__device__ __forceinline__ void cpa_commit() {
    asm volatile("cp.async.commit_group;");
}

// ---------------------------------------------------------------------------
// fp32 -> tf32 pre-conversion (3 big inputs / 4 weights)
// ---------------------------------------------------------------------------
__global__ void cvt3_kernel(const float* __restrict__ a, const float* __restrict__ b,
                            const float* __restrict__ c, unsigned* __restrict__ oa,
                            unsigned* __restrict__ ob, unsigned* __restrict__ oc) {
    const float* s = (blockIdx.y == 0) ? a : (blockIdx.y == 1) ? b : c;
    unsigned* d    = (blockIdx.y == 0) ? oa : (blockIdx.y == 1) ? ob : oc;
    const int i = (blockIdx.x * 256 + threadIdx.x) * 4;
    float4 v = *(const float4*)(s + i);
    *(uint4*)(d + i) = make_uint4(f2tf(v.x), f2tf(v.y), f2tf(v.z), f2tf(v.w));
}
__global__ void cvtW_kernel(const float* __restrict__ w0, const float* __restrict__ w1,
                            const float* __restrict__ w2, const float* __restrict__ w3,
                            unsigned* __restrict__ dst) {
    const float* s = (blockIdx.y == 0) ? w0 : (blockIdx.y == 1) ? w1
                     : (blockIdx.y == 2) ? w2 : w3;
    unsigned* d = dst + (size_t)blockIdx.y * WELEM;
    const int i = (blockIdx.x * 256 + threadIdx.x) * 4;
    float4 v = *(const float4*)(s + i);
    *(uint4*)(d + i) = make_uint4(f2tf(v.x), f2tf(v.y), f2tf(v.z), f2tf(v.w));
}

// ---------------------------------------------------------------------------
// TF32 SGEMM v3: C[4096,1024] = A @ W + bias (+ physics), A/W pre-tf32.
// CTA tile 128x256, BK=32, 3-stage cp.async ring, 8 warps (2m x 4n),
// warp tile 64x64 (1.0 LDS per HMMA). Grid (4,32)=128 CTAs = one clean wave.
// As[m][k] stride 36 (banks 4*gr+gc); Bs[k][n] stride 264 (banks 8*gc+gr).
// ---------------------------------------------------------------------------
#define V3_AS_STG 4608              // 128*36
#define V3_BS_STG 8448              // 32*264
#define V3_NST    3
#define V3_SMEM_BYTES ((V3_AS_STG + V3_BS_STG) * V3_NST * 4)   // 156672
#define V3_KIT 32

__global__ __launch_bounds__(256, 1)
void sgemm_tf32_v3(const unsigned* __restrict__ A, const unsigned* __restrict__ W,
                   const float* __restrict__ bias, void* __restrict__ Cout,
                   int out_tf32, float oscale,
                   const float* __restrict__ phys, const float* __restrict__ Pw,
                   const float* __restrict__ pb) {
    extern __shared__ unsigned sg[];
    unsigned* AsB = sg;                           // [3][4608]
    unsigned* BsB = sg + V3_NST * V3_AS_STG;      // [3][8448]
    const unsigned sA = (unsigned)__cvta_generic_to_shared(AsB);
    const unsigned sB = (unsigned)__cvta_generic_to_shared(BsB);

    const int t    = threadIdx.x;
    const int w    = t >> 5;
    const int lane = t & 31;
    const int wm   = w >> 2;          // 0..1
    const int wn   = w & 3;           // 0..3
    const int gr   = lane >> 2;       // 0..7
    const int gc   = lane & 3;        // 0..3
    const int n0   = blockIdx.x * 256;
    const int m0   = blockIdx.y * 128;

    float c[4][8][4];
#pragma unroll
    for (int mi = 0; mi < 4; mi++)
#pragma unroll
        for (int ni = 0; ni < 8; ni++)
#pragma unroll
            for (int r = 0; r < 4; r++) c[mi][ni][r] = 0.f;

    // cp.async one stage: A 128x32 (1024 chunks, 4/thread), B 32x256 (2048, 8/thread)
    auto issue = [&](int stage, int k0) {
#pragma unroll
        for (int i = 0; i < 4; i++) {
            const int ca = t + i * 256;
            const int ar = ca >> 3, ac = (ca & 7) * 4;
            cpa16(sA + (stage * V3_AS_STG + ar * 36 + ac) * 4,
                  A + (size_t)(m0 + ar) * DIM + k0 + ac);
        }
#pragma unroll
        for (int i = 0; i < 8; i++) {
            const int cb = t + i * 256;
            const int br = cb >> 6, bc = (cb & 63) * 4;
            cpa16(sB + (stage * V3_BS_STG + br * 264 + bc) * 4,
                  W + (size_t)(k0 + br) * DIM + n0 + bc);
        }
        cpa_commit();
    };

    issue(0, 0);
    issue(1, 32);

    int st = 0;
    for (int it = 0; it < V3_KIT; it++) {
        if (it + 2 < V3_KIT) {
            const int ns = (it + 2) % 3;
            issue(ns, (it + 2) * 32);
            asm volatile("cp.async.wait_group 2;");
        } else if (it + 2 == V3_KIT) {
            asm volatile("cp.async.wait_group 1;");
        } else {
            asm volatile("cp.async.wait_group 0;");
        }
        __syncthreads();

        const unsigned* Asb = AsB + st * V3_AS_STG;
        const unsigned* Bsb = BsB + st * V3_BS_STG;
#pragma unroll
        for (int ks = 0; ks < 4; ks++) {
            unsigned a[4][4];
#pragma unroll
            for (int mi = 0; mi < 4; mi++) {
                const int mr = wm * 64 + mi * 16 + gr;
                a[mi][0] = Asb[mr * 36 + ks * 8 + gc];
                a[mi][1] = Asb[(mr + 8) * 36 + ks * 8 + gc];
                a[mi][2] = Asb[mr * 36 + ks * 8 + gc + 4];
                a[mi][3] = Asb[(mr + 8) * 36 + ks * 8 + gc + 4];
            }
            unsigned b[8][2];
#pragma unroll
            for (int ni = 0; ni < 8; ni++) {
                const int nc = wn * 64 + ni * 8 + gr;
                b[ni][0] = Bsb[(ks * 8 + gc) * 264 + nc];
                b[ni][1] = Bsb[(ks * 8 + gc + 4) * 264 + nc];
            }
#pragma unroll
            for (int mi = 0; mi < 4; mi++)
#pragma unroll
                for (int ni = 0; ni < 8; ni++)
                    mma_tf32(c[mi][ni], a[mi][0], a[mi][1], a[mi][2], a[mi][3],
                             b[ni][0], b[ni][1]);
        }
        __syncthreads();
        st = (st + 1) % 3;
    }

    // Epilogue: bias (+ optional physics fold for K projection)
    const float pbv = phys ? pb[0] : 0.f;
#pragma unroll
    for (int mi = 0; mi < 4; mi++) {
#pragma unroll
        for (int h2 = 0; h2 < 2; h2++) {
            const int m = m0 + wm * 64 + mi * 16 + gr + h2 * 8;
            float p0 = 0.f, p1 = 0.f, p2 = 0.f;
            int jjb = 0;
            if (phys) {
                const int bi = m >> 11;
                const int sq = m & 2047;
                const float* ph = phys + (size_t)((bi << 7) + (sq >> 4)) * 3;
                p0 = ph[0]; p1 = ph[1]; p2 = ph[2];
                jjb = (sq & 15) << 6;
            }
#pragma unroll
            for (int ni = 0; ni < 8; ni++) {
                const int n = n0 + wn * 64 + ni * 8 + 2 * gc;
                float v0 = c[mi][ni][h2 * 2 + 0] + bias[n];
                float v1 = c[mi][ni][h2 * 2 + 1] + bias[n + 1];
                if (phys) {
                    const int j0 = jjb + (n & 63);
                    v0 += pbv * (p0 * Pw[j0]     + p1 * Pw[1024 + j0]     + p2 * Pw[2048 + j0]);
                    v1 += pbv * (p0 * Pw[j0 + 1] + p1 * Pw[1024 + j0 + 1] + p2 * Pw[2048 + j0 + 1]);
                }
                if (out_tf32) {
                    *(uint2*)&((unsigned*)Cout)[(size_t)m * DIM + n] =
                        make_uint2(f2tf(v0 * oscale), f2tf(v1 * oscale));
                } else {
                    *(float2*)&((float*)Cout)[(size_t)m * DIM + n] = make_float2(v0, v1);
                }
            }
        }
    }
}

// ---------------------------------------------------------------------------
// Flash attention (unchanged from passing R6 kernel, 575.6us baseline)
// ---------------------------------------------------------------------------
#define QS_OFF 0
#define KS_OFF 8704
#define VS_OFF 13056
#define PS_OFF 17664
#define ATTN_SMEM_BYTES ((17664 + 128 * 68) * 4)   // 105472

__global__ __launch_bounds__(256, 2)
void attn_tf32_v2(const unsigned* __restrict__ Q, const unsigned* __restrict__ K,
                  const unsigned* __restrict__ V, unsigned* __restrict__ O) {
    extern __shared__ unsigned sm_u[];
    unsigned* Qs = sm_u + QS_OFF;
    unsigned* Ks = sm_u + KS_OFF;
    unsigned* Vs = sm_u + VS_OFF;
    unsigned* Ps = sm_u + PS_OFF;
    const unsigned sQ = (unsigned)__cvta_generic_to_shared(Qs);
    const unsigned sK = (unsigned)__cvta_generic_to_shared(Ks);
    const unsigned sV = (unsigned)__cvta_generic_to_shared(Vs);

    const int t    = threadIdx.x;
    const int w    = t >> 5;
    const int lane = t & 31;
    const int gr   = lane >> 2;
    const int gc   = lane & 3;
    const int qw   = w * 16;
    const int qb   = blockIdx.x;
    const int h    = blockIdx.y;
    const int b    = blockIdx.z;
    const int q0   = qb * 128;

    const unsigned* Qg = Q + ((size_t)(b * SEQ + q0)) * DIM + h * DKH;
    const unsigned* Kg = K + ((size_t)b * SEQ) * DIM + h * DKH;
    const unsigned* Vg = V + ((size_t)b * SEQ) * DIM + h * DKH;

#pragma unroll
    for (int i = 0; i < 8; i++) {
        const int cq = t + i * 256;
        const int r = cq >> 4, d = (cq & 15) * 4;
        cpa16(sQ + (r * 68 + d) * 4, Qg + (size_t)r * DIM + d);
    }
    cpa_commit();

    auto issueK = [&](int kt) {
#pragma unroll
        for (int i = 0; i < 4; i++) {
            const int cc = t + i * 256;
            const int r = cc >> 4, d = (cc & 15) * 4;
            cpa16(sK + (r * 68 + d) * 4, Kg + (size_t)(kt * 64 + r) * DIM + d);
        }
        cpa_commit();
    };
    auto issueV = [&](int kt) {
#pragma unroll
        for (int i = 0; i < 4; i++) {
            const int cc = t + i * 256;
            const int r = cc >> 4, d = (cc & 15) * 4;
            cpa16(sV + (r * 72 + d) * 4, Vg + (size_t)(kt * 64 + r) * DIM + d);
        }
        cpa_commit();
    };

    issueK(0);
    issueV(0);

    float m0 = -1e30f, m1 = -1e30f, l0 = 0.f, l1 = 0.f;
    float o[8][4];
#pragma unroll
    for (int di = 0; di < 8; di++)
#pragma unroll
        for (int r = 0; r < 4; r++) o[di][r] = 0.f;

    for (int kt = 0; kt < SEQ / 64; kt++) {
        asm volatile("cp.async.wait_group 0;");
        __syncthreads();

        float s[8][4];
#pragma unroll
        for (int ni = 0; ni < 8; ni++)
#pragma unroll
            for (int r = 0; r < 4; r++) s[ni][r] = 0.f;
#pragma unroll
        for (int ks = 0; ks < 8; ks++) {
            const unsigned a0 = Qs[(qw + gr) * 68 + ks * 8 + gc];
            const unsigned a1 = Qs[(qw + gr + 8) * 68 + ks * 8 + gc];
            const unsigned a2 = Qs[(qw + gr) * 68 + ks * 8 + gc + 4];
            const unsigned a3 = Qs[(qw + gr + 8) * 68 + ks * 8 + gc + 4];
#pragma unroll
            for (int ni = 0; ni < 8; ni++) {
                const unsigned b0 = Ks[(ni * 8 + gr) * 68 + ks * 8 + gc];
                const unsigned b1 = Ks[(ni * 8 + gr) * 68 + ks * 8 + gc + 4];
                mma_tf32(s[ni], a0, a1, a2, a3, b0, b1);
            }
        }
        __syncthreads();
        if (kt + 1 < SEQ / 64) issueK(kt + 1);

        float mx0 = -1e30f, mx1 = -1e30f;
#pragma unroll
        for (int ni = 0; ni < 8; ni++) {
            mx0 = fmaxf(mx0, fmaxf(s[ni][0], s[ni][1]));
            mx1 = fmaxf(mx1, fmaxf(s[ni][2], s[ni][3]));
        }
        mx0 = fmaxf(mx0, __shfl_xor_sync(0xffffffffu, mx0, 1));
        mx0 = fmaxf(mx0, __shfl_xor_sync(0xffffffffu, mx0, 2));
        mx1 = fmaxf(mx1, __shfl_xor_sync(0xffffffffu, mx1, 1));
        mx1 = fmaxf(mx1, __shfl_xor_sync(0xffffffffu, mx1, 2));
        const float mn0 = fmaxf(m0, mx0), mn1 = fmaxf(m1, mx1);
        const float al0 = __expf(m0 - mn0), al1 = __expf(m1 - mn1);
        m0 = mn0; m1 = mn1;
        float rs0 = 0.f, rs1 = 0.f;
#pragma unroll
        for (int ni = 0; ni < 8; ni++) {
            s[ni][0] = __expf(s[ni][0] - mn0);
            s[ni][1] = __expf(s[ni][1] - mn0);
            s[ni][2] = __expf(s[ni][2] - mn1);
            s[ni][3] = __expf(s[ni][3] - mn1);
            rs0 += s[ni][0] + s[ni][1];
            rs1 += s[ni][2] + s[ni][3];
        }
        rs0 += __shfl_xor_sync(0xffffffffu, rs0, 1);
        rs0 += __shfl_xor_sync(0xffffffffu, rs0, 2);
        rs1 += __shfl_xor_sync(0xffffffffu, rs1, 1);
        rs1 += __shfl_xor_sync(0xffffffffu, rs1, 2);
        l0 = l0 * al0 + rs0;
        l1 = l1 * al1 + rs1;

#pragma unroll
        for (int ni = 0; ni < 8; ni++) {
            *(uint2*)&Ps[(qw + gr) * 68 + ni * 8 + 2 * gc] =
                make_uint2(f2tf(s[ni][0]), f2tf(s[ni][1]));
            *(uint2*)&Ps[(qw + gr + 8) * 68 + ni * 8 + 2 * gc] =
                make_uint2(f2tf(s[ni][2]), f2tf(s[ni][3]));
        }
#pragma unroll
        for (int di = 0; di < 8; di++) {
            o[di][0] *= al0; o[di][1] *= al0;
            o[di][2] *= al1; o[di][3] *= al1;
        }
        __syncwarp();

#pragma unroll
        for (int ks = 0; ks < 8; ks++) {
            const unsigned a0 = Ps[(qw + gr) * 68 + ks * 8 + gc];
            const unsigned a1 = Ps[(qw + gr + 8) * 68 + ks * 8 + gc];
            const unsigned a2 = Ps[(qw + gr) * 68 + ks * 8 + gc + 4];
            const unsigned a3 = Ps[(qw + gr + 8) * 68 + ks * 8 + gc + 4];
#pragma unroll
            for (int di = 0; di < 8; di++) {
                const unsigned b0 = Vs[(ks * 8 + gc) * 72 + di * 8 + gr];
                const unsigned b1 = Vs[(ks * 8 + gc + 4) * 72 + di * 8 + gr];
                mma_tf32(o[di], a0, a1, a2, a3, b0, b1);
            }
        }
        __syncthreads();
        if (kt + 1 < SEQ / 64) issueV(kt + 1);
    }

    const float i0 = 1.f / l0, i1 = 1.f / l1;
    const size_t r0 = (size_t)(b * SEQ + q0 + qw + gr) * DIM + h * DKH;
    const size_t r1 = (size_t)(b * SEQ + q0 + qw + gr + 8) * DIM + h * DKH;
#pragma unroll
    for (int di = 0; di < 8; di++) {
        const int col = di * 8 + 2 * gc;
        *(uint2*)&O[r0 + col] = make_uint2(f2tf(o[di][0] * i0), f2tf(o[di][1] * i0));
        *(uint2*)&O[r1 + col] = make_uint2(f2tf(o[di][2] * i1), f2tf(o[di][3] * i1));
    }
}

// ---------------------------------------------------------------------------
// Launch
// ---------------------------------------------------------------------------
extern "C" void kernel_launch(void* const* d_in, const int* in_sizes, int n_in,
                              void* d_out, int out_size) {
    const float* query  = (const float*)d_in[0];
    const float* key_in = (const float*)d_in[1];
    const float* value  = (const float*)d_in[2];
    const float* phys   = (const float*)d_in[3];
    const float* bq     = (const float*)d_in[5];
    const float* bk     = (const float*)d_in[7];
    const float* bv     = (const float*)d_in[9];
    const float* bo     = (const float*)d_in[11];
    const float* Pw     = (const float*)d_in[12];
    const float* pb     = (const float*)d_in[13];
    float* out          = (float*)d_out;

    unsigned *pQ, *pK, *pV, *pC, *tA0, *tA1, *tA2, *tW;
    cudaGetSymbolAddress((void**)&pQ,  g_Q);
    cudaGetSymbolAddress((void**)&pK,  g_K);
    cudaGetSymbolAddress((void**)&pV,  g_V);
    cudaGetSymbolAddress((void**)&pC,  g_ctx);
    cudaGetSymbolAddress((void**)&tA0, g_tA0);
    cudaGetSymbolAddress((void**)&tA1, g_tA1);
    cudaGetSymbolAddress((void**)&tA2, g_tA2);
    cudaGetSymbolAddress((void**)&tW,  g_tW);

    cudaFuncSetAttribute(sgemm_tf32_v3, cudaFuncAttributeMaxDynamicSharedMemorySize,
                         V3_SMEM_BYTES);
    cudaFuncSetAttribute(attn_tf32_v2, cudaFuncAttributeMaxDynamicSharedMemorySize,
                         ATTN_SMEM_BYTES);

    // Pre-convert inputs and weights to tf32
    cvt3_kernel<<<dim3(NELEM / 1024, 3), 256>>>(query, key_in, value, tA0, tA1, tA2);
    cvtW_kernel<<<dim3(WELEM / 1024, 4), 256>>>(
        (const float*)d_in[4], (const float*)d_in[6], (const float*)d_in[8],
        (const float*)d_in[10], tW);

    dim3 gg(DIM / 256, MROWS / 128);   // (4, 32) = 128 CTAs, one clean wave
    sgemm_tf32_v3<<<gg, 256, V3_SMEM_BYTES>>>(tA0, tW + 0 * WELEM, bq, pQ, 1, 0.125f,
                                              nullptr, nullptr, nullptr);
    sgemm_tf32_v3<<<gg, 256, V3_SMEM_BYTES>>>(tA1, tW + 1 * WELEM, bk, pK, 1, 1.0f,
                                              phys, Pw, pb);
    sgemm_tf32_v3<<<gg, 256, V3_SMEM_BYTES>>>(tA2, tW + 2 * WELEM, bv, pV, 1, 1.0f,
                                              nullptr, nullptr, nullptr);

    dim3 ga(SEQ / 128, HEADS, 2);
    attn_tf32_v2<<<ga, 256, ATTN_SMEM_BYTES>>>(pQ, pK, pV, pC);

    sgemm_tf32_v3<<<gg, 256, V3_SMEM_BYTES>>>(pC, tW + 3 * WELEM, bo, out, 0, 1.0f,
                                              nullptr, nullptr, nullptr);
}

// round 12
// speedup vs baseline: 7.2599x; 1.1125x over previous
#include <cuda_runtime.h>
#include <cuda_fp16.h>
#include <cstdint>

#define MROWS 4096
#define DIM   1024
#define HEADS 16
#define DKH   64
#define SEQ   2048
#define NELEM (MROWS * DIM)
#define WELEM (DIM * DIM)

// ---------------------------------------------------------------------------
// Scratch (device globals; no allocation allowed)
// ---------------------------------------------------------------------------
__device__ __half g_Qh[NELEM];      // Q proj (pre-scaled 0.125)
__device__ __half g_Kh[NELEM];      // K proj (+physics fold)
__device__ __half g_Vh[NELEM];      // V proj [m][n]
__device__ __half g_Vt[NELEM];      // V transposed: [(b*16+h)*64+dk][s]
__device__ __half g_Ch[NELEM];      // attention ctx
__device__ __half g_hA0[NELEM];     // query  (fp16)
__device__ __half g_hA1[NELEM];     // key_in (fp16)
__device__ __half g_hA2[NELEM];     // value  (fp16)
__device__ __half g_hWt[4 * WELEM]; // W^T [N][K] fp16

// ---------------------------------------------------------------------------
// Helpers
// ---------------------------------------------------------------------------
__device__ __forceinline__ unsigned f2h2(float x, float y) {
    __half2 h = __floats2half2_rn(x, y);
    return *(unsigned*)&h;
}
__device__ __forceinline__ void mma_f16(float c[4], unsigned a0, unsigned a1,
                                        unsigned a2, unsigned a3,
                                        unsigned b0, unsigned b1) {
    asm volatile(
        "mma.sync.aligned.m16n8k16.row.col.f32.f16.f16.f32 "
        "{%0,%1,%2,%3}, {%4,%5,%6,%7}, {%8,%9}, {%0,%1,%2,%3};"
        : "+f"(c[0]), "+f"(c[1]), "+f"(c[2]), "+f"(c[3])
        : "r"(a0), "r"(a1), "r"(a2), "r"(a3), "r"(b0), "r"(b1));
}
__device__ __forceinline__ void cpa16(unsigned saddr, const void* g) {
    asm volatile("cp.async.cg.shared.global [%0], [%1], 16;" :: "r"(saddr), "l"(g));
}
__device__ __forceinline__ void cpa_commit() {
    asm volatile("cp.async.commit_group;");
}

// ---------------------------------------------------------------------------
// fp32 -> fp16 pre-conversion (3 inputs) and weight transpose+fp16
// ---------------------------------------------------------------------------
__global__ void cvt3_kernel(const float* __restrict__ a, const float* __restrict__ b,
                            const float* __restrict__ c, __half* __restrict__ oa,
                            __half* __restrict__ ob, __half* __restrict__ oc) {
    const float* s = (blockIdx.y == 0) ? a : (blockIdx.y == 1) ? b : c;
    __half* d      = (blockIdx.y == 0) ? oa : (blockIdx.y == 1) ? ob : oc;
    const int i = (blockIdx.x * 256 + threadIdx.x) * 4;
    float4 v = *(const float4*)(s + i);
    uint2 o;
    o.x = f2h2(v.x, v.y);
    o.y = f2h2(v.z, v.w);
    *(uint2*)(d + i) = o;
}
// dst[n*K + k] = half(w[k*N + n])
__global__ void cvtWT_kernel(const float* __restrict__ w0, const float* __restrict__ w1,
                             const float* __restrict__ w2, const float* __restrict__ w3,
                             __half* __restrict__ dst) {
    __shared__ float tile[32][33];
    const float* s = (blockIdx.z == 0) ? w0 : (blockIdx.z == 1) ? w1
                     : (blockIdx.z == 2) ? w2 : w3;
    __half* d = dst + (size_t)blockIdx.z * WELEM;
    const int tx = threadIdx.x, ty = threadIdx.y;   // 32 x 8
    const int k0 = blockIdx.y * 32, n0 = blockIdx.x * 32;
#pragma unroll
    for (int j = 0; j < 32; j += 8)
        tile[ty + j][tx] = s[(size_t)(k0 + ty + j) * DIM + n0 + tx];
    __syncthreads();
#pragma unroll
    for (int j = 0; j < 32; j += 8)
        d[(size_t)(n0 + ty + j) * DIM + k0 + tx] = __float2half_rn(tile[tx][ty + j]);
}
// Vt[(b*1024 + n)][s] = Vh[(b*2048+s)][n]
__global__ void transposeV_kernel(const __half* __restrict__ src, __half* __restrict__ dst) {
    __shared__ __half tile[32][34];
    const int b = blockIdx.z;
    const int s0 = blockIdx.x * 32, n0 = blockIdx.y * 32;
    const int tx = threadIdx.x, ty = threadIdx.y;   // 32 x 8
#pragma unroll
    for (int j = 0; j < 32; j += 8)
        tile[ty + j][tx] = src[(size_t)(b * SEQ + s0 + ty + j) * DIM + n0 + tx];
    __syncthreads();
#pragma unroll
    for (int j = 0; j < 32; j += 8)
        dst[(size_t)(b * DIM + n0 + ty + j) * SEQ + s0 + tx] = tile[tx][ty + j];
}

// ---------------------------------------------------------------------------
// FP16 GEMM: C[4096,1024] = A[4096,1024] @ Wt[N][K]^T + bias (+ physics)
// CTA 128x256, BK=32 (2 x k16), 4-stage cp.async, 8 warps (2m x 4n), 64x64 warp.
// As[m][k] stride 40 halfs; Bs[n][k] stride 40 halfs (both conflict-free).
// ---------------------------------------------------------------------------
#define H_AS_STG 5120               // 128*40 halfs
#define H_BS_STG 10240              // 256*40 halfs
#define H_NST    4
#define H_SMEM_BYTES ((H_AS_STG + H_BS_STG) * H_NST * 2)   // 122880
#define H_KIT 32

__global__ __launch_bounds__(256, 1)
void sgemm_f16(const __half* __restrict__ A, const __half* __restrict__ Wt,
               const float* __restrict__ bias, void* __restrict__ Cout,
               int out_half, float oscale,
               const float* __restrict__ phys, const float* __restrict__ Pw,
               const float* __restrict__ pb) {
    extern __shared__ __half sh[];
    __half* AsB = sh;                          // [4][5120]
    __half* BsB = sh + H_NST * H_AS_STG;       // [4][10240]
    const unsigned sA = (unsigned)__cvta_generic_to_shared(AsB);
    const unsigned sB = (unsigned)__cvta_generic_to_shared(BsB);

    const int t    = threadIdx.x;
    const int w    = t >> 5;
    const int lane = t & 31;
    const int wm   = w >> 2;          // 0..1
    const int wn   = w & 3;           // 0..3
    const int gr   = lane >> 2;       // 0..7
    const int gc   = lane & 3;        // 0..3
    const int n0   = blockIdx.x * 256;
    const int m0   = blockIdx.y * 128;

    float c[4][8][4];
#pragma unroll
    for (int mi = 0; mi < 4; mi++)
#pragma unroll
        for (int ni = 0; ni < 8; ni++)
#pragma unroll
            for (int r = 0; r < 4; r++) c[mi][ni][r] = 0.f;

    // one stage: A 128x32 halfs (512 x16B chunks, 2/thr), B 256x32 (1024, 4/thr)
    auto issue = [&](int stage, int k0) {
#pragma unroll
        for (int i = 0; i < 2; i++) {
            const int ca = t + i * 256;
            const int ar = ca >> 2, ac = (ca & 3) * 8;
            cpa16(sA + (stage * H_AS_STG + ar * 40 + ac) * 2,
                  A + (size_t)(m0 + ar) * DIM + k0 + ac);
        }
#pragma unroll
        for (int i = 0; i < 4; i++) {
            const int cb = t + i * 256;
            const int br = cb >> 2, bc = (cb & 3) * 8;
            cpa16(sB + (stage * H_BS_STG + br * 40 + bc) * 2,
                  Wt + (size_t)(n0 + br) * DIM + k0 + bc);
        }
        cpa_commit();
    };

    issue(0, 0);
    issue(1, 32);
    issue(2, 64);

    for (int it = 0; it < H_KIT; it++) {
        if (it + 3 < H_KIT) {
            issue((it + 3) & 3, (it + 3) * 32);
            asm volatile("cp.async.wait_group 3;");
        } else if (it == H_KIT - 3) {
            asm volatile("cp.async.wait_group 2;");
        } else if (it == H_KIT - 2) {
            asm volatile("cp.async.wait_group 1;");
        } else {
            asm volatile("cp.async.wait_group 0;");
        }
        __syncthreads();

        const __half* Asb = AsB + (it & 3) * H_AS_STG;
        const __half* Bsb = BsB + (it & 3) * H_BS_STG;
#pragma unroll
        for (int ks = 0; ks < 2; ks++) {
            const int ko = ks * 16;
            unsigned a[4][4];
#pragma unroll
            for (int mi = 0; mi < 4; mi++) {
                const int mr = wm * 64 + mi * 16 + gr;
                a[mi][0] = *(const unsigned*)&Asb[mr * 40 + ko + 2 * gc];
                a[mi][1] = *(const unsigned*)&Asb[(mr + 8) * 40 + ko + 2 * gc];
                a[mi][2] = *(const unsigned*)&Asb[mr * 40 + ko + 2 * gc + 8];
                a[mi][3] = *(const unsigned*)&Asb[(mr + 8) * 40 + ko + 2 * gc + 8];
            }
            unsigned b[8][2];
#pragma unroll
            for (int ni = 0; ni < 8; ni++) {
                const int nc = wn * 64 + ni * 8 + gr;
                b[ni][0] = *(const unsigned*)&Bsb[nc * 40 + ko + 2 * gc];
                b[ni][1] = *(const unsigned*)&Bsb[nc * 40 + ko + 2 * gc + 8];
            }
#pragma unroll
            for (int mi = 0; mi < 4; mi++)
#pragma unroll
                for (int ni = 0; ni < 8; ni++)
                    mma_f16(c[mi][ni], a[mi][0], a[mi][1], a[mi][2], a[mi][3],
                            b[ni][0], b[ni][1]);
        }
        __syncthreads();
    }

    // Epilogue: bias (+ physics fold for K projection)
    const float pbv = phys ? pb[0] : 0.f;
#pragma unroll
    for (int mi = 0; mi < 4; mi++) {
#pragma unroll
        for (int h2 = 0; h2 < 2; h2++) {
            const int m = m0 + wm * 64 + mi * 16 + gr + h2 * 8;
            float p0 = 0.f, p1 = 0.f, p2 = 0.f;
            int jjb = 0;
            if (phys) {
                const int bi = m >> 11;
                const int sq = m & 2047;
                const float* ph = phys + (size_t)((bi << 7) + (sq >> 4)) * 3;
                p0 = ph[0]; p1 = ph[1]; p2 = ph[2];
                jjb = (sq & 15) << 6;
            }
#pragma unroll
            for (int ni = 0; ni < 8; ni++) {
                const int n = n0 + wn * 64 + ni * 8 + 2 * gc;
                float v0 = c[mi][ni][h2 * 2 + 0] + bias[n];
                float v1 = c[mi][ni][h2 * 2 + 1] + bias[n + 1];
                if (phys) {
                    const int j0 = jjb + (n & 63);
                    v0 += pbv * (p0 * Pw[j0]     + p1 * Pw[1024 + j0]     + p2 * Pw[2048 + j0]);
                    v1 += pbv * (p0 * Pw[j0 + 1] + p1 * Pw[1024 + j0 + 1] + p2 * Pw[2048 + j0 + 1]);
                }
                if (out_half) {
                    *(unsigned*)&((__half*)Cout)[(size_t)m * DIM + n] =
                        f2h2(v0 * oscale, v1 * oscale);
                } else {
                    *(float2*)&((float*)Cout)[(size_t)m * DIM + n] = make_float2(v0, v1);
                }
            }
        }
    }
}

// ---------------------------------------------------------------------------
// FP16 flash attention. CTA = (b, h, 128 q rows); 8 warps, 16 q rows each.
// P stays in registers (GEMM1 c-frag == GEMM2 a-frag layout).
// SMEM (halfs, stride 72): Qs[128][72] | Ks[64][72] | Vs(dk-major)[64][72]
// ---------------------------------------------------------------------------
#define AQ_OFF 0
#define AK_OFF 9216
#define AV_OFF 13824
#define A_SMEM_BYTES ((13824 + 64 * 72) * 2)   // 36864

__global__ __launch_bounds__(256, 2)
void attn_f16(const __half* __restrict__ Q, const __half* __restrict__ K,
              const __half* __restrict__ Vt, __half* __restrict__ O) {
    extern __shared__ __half sm_h[];
    __half* Qs = sm_h + AQ_OFF;
    __half* Ks = sm_h + AK_OFF;
    __half* Vs = sm_h + AV_OFF;
    const unsigned sQ = (unsigned)__cvta_generic_to_shared(Qs);
    const unsigned sK = (unsigned)__cvta_generic_to_shared(Ks);
    const unsigned sV = (unsigned)__cvta_generic_to_shared(Vs);

    const int t    = threadIdx.x;
    const int w    = t >> 5;
    const int lane = t & 31;
    const int gr   = lane >> 2;
    const int gc   = lane & 3;
    const int qw   = w * 16;
    const int qb   = blockIdx.x;
    const int h    = blockIdx.y;
    const int b    = blockIdx.z;
    const int q0   = qb * 128;

    const __half* Qg  = Q  + ((size_t)(b * SEQ + q0)) * DIM + h * DKH;
    const __half* Kg  = K  + ((size_t)b * SEQ) * DIM + h * DKH;
    const __half* Vtg = Vt + (size_t)(b * DIM + h * DKH) * SEQ;

    // Q tile: 128 x 64 halfs = 1024 chunks (4/thread)
#pragma unroll
    for (int i = 0; i < 4; i++) {
        const int cq = t + i * 256;
        const int r = cq >> 3, d = (cq & 7) * 8;
        cpa16(sQ + (r * 72 + d) * 2, Qg + (size_t)r * DIM + d);
    }
    cpa_commit();

    auto issueK = [&](int kt) {
#pragma unroll
        for (int i = 0; i < 2; i++) {
            const int cc = t + i * 256;       // 512 chunks (64 x 8)
            const int r = cc >> 3, d = (cc & 7) * 8;
            cpa16(sK + (r * 72 + d) * 2, Kg + (size_t)(kt * 64 + r) * DIM + d);
        }
        cpa_commit();
    };
    auto issueV = [&](int kt) {
#pragma unroll
        for (int i = 0; i < 2; i++) {
            const int cc = t + i * 256;       // rows = dk, cols = seq chunk
            const int r = cc >> 3, d = (cc & 7) * 8;
            cpa16(sV + (r * 72 + d) * 2, Vtg + (size_t)r * SEQ + kt * 64 + d);
        }
        cpa_commit();
    };

    issueK(0);
    issueV(0);

    float m0 = -1e30f, m1 = -1e30f, l0 = 0.f, l1 = 0.f;
    float o[8][4];
#pragma unroll
    for (int di = 0; di < 8; di++)
#pragma unroll
        for (int r = 0; r < 4; r++) o[di][r] = 0.f;

    for (int kt = 0; kt < SEQ / 64; kt++) {
        asm volatile("cp.async.wait_group 0;");
        __syncthreads();

        // GEMM1: S[16q x 64k], 4 k16 steps over dk
        float s[8][4];
#pragma unroll
        for (int ni = 0; ni < 8; ni++)
#pragma unroll
            for (int r = 0; r < 4; r++) s[ni][r] = 0.f;
#pragma unroll
        for (int ks = 0; ks < 4; ks++) {
            const int ko = ks * 16;
            const unsigned a0 = *(const unsigned*)&Qs[(qw + gr) * 72 + ko + 2 * gc];
            const unsigned a1 = *(const unsigned*)&Qs[(qw + gr + 8) * 72 + ko + 2 * gc];
            const unsigned a2 = *(const unsigned*)&Qs[(qw + gr) * 72 + ko + 2 * gc + 8];
            const unsigned a3 = *(const unsigned*)&Qs[(qw + gr + 8) * 72 + ko + 2 * gc + 8];
#pragma unroll
            for (int ni = 0; ni < 8; ni++) {
                const unsigned b0 = *(const unsigned*)&Ks[(ni * 8 + gr) * 72 + ko + 2 * gc];
                const unsigned b1 = *(const unsigned*)&Ks[(ni * 8 + gr) * 72 + ko + 2 * gc + 8];
                mma_f16(s[ni], a0, a1, a2, a3, b0, b1);
            }
        }
        __syncthreads();                  // all warps done reading Ks
        if (kt + 1 < SEQ / 64) issueK(kt + 1);

        // Online softmax in registers
        float mx0 = -1e30f, mx1 = -1e30f;
#pragma unroll
        for (int ni = 0; ni < 8; ni++) {
            mx0 = fmaxf(mx0, fmaxf(s[ni][0], s[ni][1]));
            mx1 = fmaxf(mx1, fmaxf(s[ni][2], s[ni][3]));
        }
        mx0 = fmaxf(mx0, __shfl_xor_sync(0xffffffffu, mx0, 1));
        mx0 = fmaxf(mx0, __shfl_xor_sync(0xffffffffu, mx0, 2));
        mx1 = fmaxf(mx1, __shfl_xor_sync(0xffffffffu, mx1, 1));
        mx1 = fmaxf(mx1, __shfl_xor_sync(0xffffffffu, mx1, 2));
        const float mn0 = fmaxf(m0, mx0), mn1 = fmaxf(m1, mx1);
        const float al0 = __expf(m0 - mn0), al1 = __expf(m1 - mn1);
        m0 = mn0; m1 = mn1;
        float rs0 = 0.f, rs1 = 0.f;
#pragma unroll
        for (int ni = 0; ni < 8; ni++) {
            s[ni][0] = __expf(s[ni][0] - mn0);
            s[ni][1] = __expf(s[ni][1] - mn0);
            s[ni][2] = __expf(s[ni][2] - mn1);
            s[ni][3] = __expf(s[ni][3] - mn1);
            rs0 += s[ni][0] + s[ni][1];
            rs1 += s[ni][2] + s[ni][3];
        }
        rs0 += __shfl_xor_sync(0xffffffffu, rs0, 1);
        rs0 += __shfl_xor_sync(0xffffffffu, rs0, 2);
        rs1 += __shfl_xor_sync(0xffffffffu, rs1, 1);
        rs1 += __shfl_xor_sync(0xffffffffu, rs1, 2);
        l0 = l0 * al0 + rs0;
        l1 = l1 * al1 + rs1;

        // Pack P into registers: GEMM1 c-frag (row, 2gc..2gc+1) == GEMM2 a-frag
        unsigned pl[8], ph[8];
#pragma unroll
        for (int ni = 0; ni < 8; ni++) {
            pl[ni] = f2h2(s[ni][0], s[ni][1]);
            ph[ni] = f2h2(s[ni][2], s[ni][3]);
        }
#pragma unroll
        for (int di = 0; di < 8; di++) {
            o[di][0] *= al0; o[di][1] *= al0;
            o[di][2] *= al1; o[di][3] *= al1;
        }

        // GEMM2: O[16q x 64dk] += P @ V ; A from registers, B from Vs (dk-major)
#pragma unroll
        for (int ks = 0; ks < 4; ks++) {
            const int ko = ks * 16;
            const unsigned a0 = pl[2 * ks];
            const unsigned a1 = ph[2 * ks];
            const unsigned a2 = pl[2 * ks + 1];
            const unsigned a3 = ph[2 * ks + 1];
#pragma unroll
            for (int di = 0; di < 8; di++) {
                const unsigned b0 = *(const unsigned*)&Vs[(di * 8 + gr) * 72 + ko + 2 * gc];
                const unsigned b1 = *(const unsigned*)&Vs[(di * 8 + gr) * 72 + ko + 2 * gc + 8];
                mma_f16(o[di], a0, a1, a2, a3, b0, b1);
            }
        }
        __syncthreads();                  // all warps done reading Vs
        if (kt + 1 < SEQ / 64) issueV(kt + 1);
    }

    // Epilogue: normalize, store ctx as fp16 (half2 per n-pair)
    const float i0 = 1.f / l0, i1 = 1.f / l1;
    const size_t r0 = (size_t)(b * SEQ + q0 + qw + gr) * DIM + h * DKH;
    const size_t r1 = (size_t)(b * SEQ + q0 + qw + gr + 8) * DIM + h * DKH;
#pragma unroll
    for (int di = 0; di < 8; di++) {
        const int col = di * 8 + 2 * gc;
        *(unsigned*)&O[r0 + col] = f2h2(o[di][0] * i0, o[di][1] * i0);
        *(unsigned*)&O[r1 + col] = f2h2(o[di][2] * i1, o[di][3] * i1);
    }
}

// ---------------------------------------------------------------------------
// Launch
// ---------------------------------------------------------------------------
extern "C" void kernel_launch(void* const* d_in, const int* in_sizes, int n_in,
                              void* d_out, int out_size) {
    const float* query  = (const float*)d_in[0];
    const float* key_in = (const float*)d_in[1];
    const float* value  = (const float*)d_in[2];
    const float* phys   = (const float*)d_in[3];
    const float* bq     = (const float*)d_in[5];
    const float* bk     = (const float*)d_in[7];
    const float* bv     = (const float*)d_in[9];
    const float* bo     = (const float*)d_in[11];
    const float* Pw     = (const float*)d_in[12];
    const float* pb     = (const float*)d_in[13];
    float* out          = (float*)d_out;

    __half *pQ, *pK, *pV, *pVt, *pC, *hA0, *hA1, *hA2, *hW;
    cudaGetSymbolAddress((void**)&pQ,  g_Qh);
    cudaGetSymbolAddress((void**)&pK,  g_Kh);
    cudaGetSymbolAddress((void**)&pV,  g_Vh);
    cudaGetSymbolAddress((void**)&pVt, g_Vt);
    cudaGetSymbolAddress((void**)&pC,  g_Ch);
    cudaGetSymbolAddress((void**)&hA0, g_hA0);
    cudaGetSymbolAddress((void**)&hA1, g_hA1);
    cudaGetSymbolAddress((void**)&hA2, g_hA2);
    cudaGetSymbolAddress((void**)&hW,  g_hWt);

    cudaFuncSetAttribute(sgemm_f16, cudaFuncAttributeMaxDynamicSharedMemorySize,
                         H_SMEM_BYTES);
    cudaFuncSetAttribute(attn_f16, cudaFuncAttributeMaxDynamicSharedMemorySize,
                         A_SMEM_BYTES);

    // Pre-convert inputs (fp16) and weights (transpose + fp16)
    cvt3_kernel<<<dim3(NELEM / 1024, 3), 256>>>(query, key_in, value, hA0, hA1, hA2);
    cvtWT_kernel<<<dim3(32, 32, 4), dim3(32, 8)>>>(
        (const float*)d_in[4], (const float*)d_in[6], (const float*)d_in[8],
        (const float*)d_in[10], hW);

    dim3 gg(DIM / 256, MROWS / 128);   // (4, 32)
    sgemm_f16<<<gg, 256, H_SMEM_BYTES>>>(hA0, hW + 0 * WELEM, bq, pQ, 1, 0.125f,
                                         nullptr, nullptr, nullptr);
    sgemm_f16<<<gg, 256, H_SMEM_BYTES>>>(hA1, hW + 1 * WELEM, bk, pK, 1, 1.0f,
                                         phys, Pw, pb);
    sgemm_f16<<<gg, 256, H_SMEM_BYTES>>>(hA2, hW + 2 * WELEM, bv, pV, 1, 1.0f,
                                         nullptr, nullptr, nullptr);

    // V -> V^T (dk-major) for attention GEMM2 B-operand
    transposeV_kernel<<<dim3(SEQ / 32, DIM / 32, 2), dim3(32, 8)>>>(pV, pVt);

    dim3 ga(SEQ / 128, HEADS, 2);      // (16, 16, 2)
    attn_f16<<<ga, 256, A_SMEM_BYTES>>>(pQ, pK, pVt, pC);

    sgemm_f16<<<gg, 256, H_SMEM_BYTES>>>(pC, hW + 3 * WELEM, bo, out, 0, 1.0f,
                                         nullptr, nullptr, nullptr);
}

// round 13
// speedup vs baseline: 11.2429x; 1.5486x over previous
#include <cuda_runtime.h>
#include <cuda_fp16.h>
#include <cstdint>

#define MROWS 4096
#define DIM   1024
#define HEADS 16
#define DKH   64
#define SEQ   2048
#define NELEM (MROWS * DIM)
#define WELEM (DIM * DIM)

// ---------------------------------------------------------------------------
// Scratch (device globals; no allocation allowed)
// ---------------------------------------------------------------------------
__device__ __half g_Qh[NELEM];      // Q proj (pre-scaled 0.125)
__device__ __half g_Kh[NELEM];      // K proj (+physics fold)
__device__ __half g_Vh[NELEM];      // V proj [m][n]
__device__ __half g_Vt[NELEM];      // V transposed: [(b*16+h)*64+dk][s]
__device__ __half g_Ch[NELEM];      // attention ctx
__device__ __half g_hA0[NELEM];     // query  (fp16)
__device__ __half g_hA1[NELEM];     // key_in (fp16)
__device__ __half g_hA2[NELEM];     // value  (fp16)
__device__ __half g_hWt[4 * WELEM]; // W^T [N][K] fp16

// ---------------------------------------------------------------------------
// Helpers
// ---------------------------------------------------------------------------
__device__ __forceinline__ unsigned f2h2(float x, float y) {
    __half2 h = __floats2half2_rn(x, y);
    return *(unsigned*)&h;
}
__device__ __forceinline__ void mma_f16(float c[4], unsigned a0, unsigned a1,
                                        unsigned a2, unsigned a3,
                                        unsigned b0, unsigned b1) {
    asm volatile(
        "mma.sync.aligned.m16n8k16.row.col.f32.f16.f16.f32 "
        "{%0,%1,%2,%3}, {%4,%5,%6,%7}, {%8,%9}, {%0,%1,%2,%3};"
        : "+f"(c[0]), "+f"(c[1]), "+f"(c[2]), "+f"(c[3])
        : "r"(a0), "r"(a1), "r"(a2), "r"(a3), "r"(b0), "r"(b1));
}
__device__ __forceinline__ void ldsm_x4(unsigned& r0, unsigned& r1, unsigned& r2,
                                        unsigned& r3, unsigned saddr) {
    asm volatile("ldmatrix.sync.aligned.m8n8.x4.shared.b16 {%0,%1,%2,%3}, [%4];"
                 : "=r"(r0), "=r"(r1), "=r"(r2), "=r"(r3) : "r"(saddr));
}
__device__ __forceinline__ void cpa16(unsigned saddr, const void* g) {
    asm volatile("cp.async.cg.shared.global [%0], [%1], 16;" :: "r"(saddr), "l"(g));
}
__device__ __forceinline__ void cpa_commit() {
    asm volatile("cp.async.commit_group;");
}

// ---------------------------------------------------------------------------
// fp32 -> fp16 pre-conversion (3 inputs) and weight transpose+fp16
// ---------------------------------------------------------------------------
__global__ void cvt3_kernel(const float* __restrict__ a, const float* __restrict__ b,
                            const float* __restrict__ c, __half* __restrict__ oa,
                            __half* __restrict__ ob, __half* __restrict__ oc) {
    const float* s = (blockIdx.y == 0) ? a : (blockIdx.y == 1) ? b : c;
    __half* d      = (blockIdx.y == 0) ? oa : (blockIdx.y == 1) ? ob : oc;
    const int i = (blockIdx.x * 256 + threadIdx.x) * 4;
    float4 v = *(const float4*)(s + i);
    uint2 o;
    o.x = f2h2(v.x, v.y);
    o.y = f2h2(v.z, v.w);
    *(uint2*)(d + i) = o;
}
// dst[n*K + k] = half(w[k*N + n])
__global__ void cvtWT_kernel(const float* __restrict__ w0, const float* __restrict__ w1,
                             const float* __restrict__ w2, const float* __restrict__ w3,
                             __half* __restrict__ dst) {
    __shared__ float tile[32][33];
    const float* s = (blockIdx.z == 0) ? w0 : (blockIdx.z == 1) ? w1
                     : (blockIdx.z == 2) ? w2 : w3;
    __half* d = dst + (size_t)blockIdx.z * WELEM;
    const int tx = threadIdx.x, ty = threadIdx.y;   // 32 x 8
    const int k0 = blockIdx.y * 32, n0 = blockIdx.x * 32;
#pragma unroll
    for (int j = 0; j < 32; j += 8)
        tile[ty + j][tx] = s[(size_t)(k0 + ty + j) * DIM + n0 + tx];
    __syncthreads();
#pragma unroll
    for (int j = 0; j < 32; j += 8)
        d[(size_t)(n0 + ty + j) * DIM + k0 + tx] = __float2half_rn(tile[tx][ty + j]);
}
// Vt[(b*1024 + n)][s] = Vh[(b*2048+s)][n]
__global__ void transposeV_kernel(const __half* __restrict__ src, __half* __restrict__ dst) {
    __shared__ __half tile[32][34];
    const int b = blockIdx.z;
    const int s0 = blockIdx.x * 32, n0 = blockIdx.y * 32;
    const int tx = threadIdx.x, ty = threadIdx.y;   // 32 x 8
#pragma unroll
    for (int j = 0; j < 32; j += 8)
        tile[ty + j][tx] = src[(size_t)(b * SEQ + s0 + ty + j) * DIM + n0 + tx];
    __syncthreads();
#pragma unroll
    for (int j = 0; j < 32; j += 8)
        dst[(size_t)(b * DIM + n0 + ty + j) * SEQ + s0 + tx] = tile[tx][ty + j];
}

// ---------------------------------------------------------------------------
// FP16 GEMM: C[4096,1024] = A[4096,1024] @ Wt[N][K]^T + bias (+ physics)
// CTA 128x256, BK=32 (2 x k16), 4-stage cp.async, 8 warps (2m x 4n), 64x64 warp.
// Fragments loaded via ldmatrix.x4 (8 LDSM per k16 step vs 48 scalar LDS).
// As[m][k] stride 40 halfs; Bs[n][k] stride 40 halfs (conflict-free for LDSM).
// ---------------------------------------------------------------------------
#define H_AS_STG 5120               // 128*40 halfs
#define H_BS_STG 10240              // 256*40 halfs
#define H_NST    4
#define H_SMEM_BYTES ((H_AS_STG + H_BS_STG) * H_NST * 2)   // 122880
#define H_KIT 32

__global__ __launch_bounds__(256, 1)
void sgemm_f16(const __half* __restrict__ A, const __half* __restrict__ Wt,
               const float* __restrict__ bias, void* __restrict__ Cout,
               int out_half, float oscale,
               const float* __restrict__ phys, const float* __restrict__ Pw,
               const float* __restrict__ pb) {
    extern __shared__ __half sh[];
    __half* AsB = sh;                          // [4][5120]
    __half* BsB = sh + H_NST * H_AS_STG;       // [4][10240]
    const unsigned sA = (unsigned)__cvta_generic_to_shared(AsB);
    const unsigned sB = (unsigned)__cvta_generic_to_shared(BsB);

    const int t    = threadIdx.x;
    const int w    = t >> 5;
    const int lane = t & 31;
    const int wm   = w >> 2;          // 0..1
    const int wn   = w & 3;           // 0..3
    const int gr   = lane >> 2;       // 0..7
    const int gc   = lane & 3;        // 0..3
    const int n0   = blockIdx.x * 256;
    const int m0   = blockIdx.y * 128;

    // ldmatrix per-lane offsets (bytes):
    // A x4: lanes0-7 rows+0 klo | 8-15 rows+8 klo | 16-23 rows+0 khi | 24-31 rows+8 khi
    const unsigned offA = ((((lane & 7) + ((lane & 8) ? 8 : 0)) * 40) +
                           ((lane & 16) ? 8 : 0)) * 2;
    // B x4: lanes0-7 n+0 klo | 8-15 n+0 khi | 16-23 n+8 klo | 24-31 n+8 khi
    const unsigned offB = (((((lane >> 4) * 8) + (lane & 7)) * 40) +
                           ((lane & 8) ? 8 : 0)) * 2;

    float c[4][8][4];
#pragma unroll
    for (int mi = 0; mi < 4; mi++)
#pragma unroll
        for (int ni = 0; ni < 8; ni++)
#pragma unroll
            for (int r = 0; r < 4; r++) c[mi][ni][r] = 0.f;

    // one stage: A 128x32 halfs (512 x16B chunks, 2/thr), B 256x32 (1024, 4/thr)
    auto issue = [&](int stage, int k0) {
#pragma unroll
        for (int i = 0; i < 2; i++) {
            const int ca = t + i * 256;
            const int ar = ca >> 2, ac = (ca & 3) * 8;
            cpa16(sA + (stage * H_AS_STG + ar * 40 + ac) * 2,
                  A + (size_t)(m0 + ar) * DIM + k0 + ac);
        }
#pragma unroll
        for (int i = 0; i < 4; i++) {
            const int cb = t + i * 256;
            const int br = cb >> 2, bc = (cb & 3) * 8;
            cpa16(sB + (stage * H_BS_STG + br * 40 + bc) * 2,
                  Wt + (size_t)(n0 + br) * DIM + k0 + bc);
        }
        cpa_commit();
    };

    issue(0, 0);
    issue(1, 32);
    issue(2, 64);

    for (int it = 0; it < H_KIT; it++) {
        if (it + 3 < H_KIT) {
            issue((it + 3) & 3, (it + 3) * 32);
            asm volatile("cp.async.wait_group 3;");
        } else if (it == H_KIT - 3) {
            asm volatile("cp.async.wait_group 2;");
        } else if (it == H_KIT - 2) {
            asm volatile("cp.async.wait_group 1;");
        } else {
            asm volatile("cp.async.wait_group 0;");
        }
        __syncthreads();

        const unsigned aBase = sA + (it & 3) * H_AS_STG * 2;
        const unsigned bBase = sB + (it & 3) * H_BS_STG * 2;
#pragma unroll
        for (int ks = 0; ks < 2; ks++) {
            const int ko = ks * 16;
            unsigned a[4][4];
#pragma unroll
            for (int mi = 0; mi < 4; mi++)
                ldsm_x4(a[mi][0], a[mi][1], a[mi][2], a[mi][3],
                        aBase + ((wm * 64 + mi * 16) * 40 + ko) * 2 + offA);
            unsigned b[8][2];
#pragma unroll
            for (int j = 0; j < 4; j++)
                ldsm_x4(b[2 * j][0], b[2 * j][1], b[2 * j + 1][0], b[2 * j + 1][1],
                        bBase + ((wn * 64 + j * 16) * 40 + ko) * 2 + offB);
#pragma unroll
            for (int mi = 0; mi < 4; mi++)
#pragma unroll
                for (int ni = 0; ni < 8; ni++)
                    mma_f16(c[mi][ni], a[mi][0], a[mi][1], a[mi][2], a[mi][3],
                            b[ni][0], b[ni][1]);
        }
        __syncthreads();
    }

    // Epilogue: bias (+ physics fold for K projection)
    const float pbv = phys ? pb[0] : 0.f;
#pragma unroll
    for (int mi = 0; mi < 4; mi++) {
#pragma unroll
        for (int h2 = 0; h2 < 2; h2++) {
            const int m = m0 + wm * 64 + mi * 16 + gr + h2 * 8;
            float p0 = 0.f, p1 = 0.f, p2 = 0.f;
            int jjb = 0;
            if (phys) {
                const int bi = m >> 11;
                const int sq = m & 2047;
                const float* ph = phys + (size_t)((bi << 7) + (sq >> 4)) * 3;
                p0 = ph[0]; p1 = ph[1]; p2 = ph[2];
                jjb = (sq & 15) << 6;
            }
#pragma unroll
            for (int ni = 0; ni < 8; ni++) {
                const int n = n0 + wn * 64 + ni * 8 + 2 * gc;
                float v0 = c[mi][ni][h2 * 2 + 0] + bias[n];
                float v1 = c[mi][ni][h2 * 2 + 1] + bias[n + 1];
                if (phys) {
                    const int j0 = jjb + (n & 63);
                    v0 += pbv * (p0 * Pw[j0]     + p1 * Pw[1024 + j0]     + p2 * Pw[2048 + j0]);
                    v1 += pbv * (p0 * Pw[j0 + 1] + p1 * Pw[1024 + j0 + 1] + p2 * Pw[2048 + j0 + 1]);
                }
                if (out_half) {
                    *(unsigned*)&((__half*)Cout)[(size_t)m * DIM + n] =
                        f2h2(v0 * oscale, v1 * oscale);
                } else {
                    *(float2*)&((float*)Cout)[(size_t)m * DIM + n] = make_float2(v0, v1);
                }
            }
        }
    }
}

// ---------------------------------------------------------------------------
// FP16 flash attention. CTA = (b, h, 128 q rows); 8 warps, 16 q rows each.
// P stays in registers; Q/K/V fragments via ldmatrix.
// SMEM (halfs, stride 72): Qs[128][72] | Ks[64][72] | Vs(dk-major)[64][72]
// ---------------------------------------------------------------------------
#define AQ_OFF 0
#define AK_OFF 9216
#define AV_OFF 13824
#define A_SMEM_BYTES ((13824 + 64 * 72) * 2)   // 36864

__global__ __launch_bounds__(256, 2)
void attn_f16(const __half* __restrict__ Q, const __half* __restrict__ K,
              const __half* __restrict__ Vt, __half* __restrict__ O) {
    extern __shared__ __half sm_h[];
    __half* Qs = sm_h + AQ_OFF;
    __half* Ks = sm_h + AK_OFF;
    __half* Vs = sm_h + AV_OFF;
    const unsigned sQ = (unsigned)__cvta_generic_to_shared(Qs);
    const unsigned sK = (unsigned)__cvta_generic_to_shared(Ks);
    const unsigned sV = (unsigned)__cvta_generic_to_shared(Vs);

    const int t    = threadIdx.x;
    const int w    = t >> 5;
    const int lane = t & 31;
    const int gr   = lane >> 2;
    const int gc   = lane & 3;
    const int qw   = w * 16;
    const int qb   = blockIdx.x;
    const int h    = blockIdx.y;
    const int b    = blockIdx.z;
    const int q0   = qb * 128;

    // ldmatrix per-lane offsets (bytes), stride 72 halfs
    const unsigned offA = ((((lane & 7) + ((lane & 8) ? 8 : 0)) * 72) +
                           ((lane & 16) ? 8 : 0)) * 2;
    const unsigned offB = (((((lane >> 4) * 8) + (lane & 7)) * 72) +
                           ((lane & 8) ? 8 : 0)) * 2;

    const __half* Qg  = Q  + ((size_t)(b * SEQ + q0)) * DIM + h * DKH;
    const __half* Kg  = K  + ((size_t)b * SEQ) * DIM + h * DKH;
    const __half* Vtg = Vt + (size_t)(b * DIM + h * DKH) * SEQ;

    // Q tile: 128 x 64 halfs = 1024 chunks (4/thread)
#pragma unroll
    for (int i = 0; i < 4; i++) {
        const int cq = t + i * 256;
        const int r = cq >> 3, d = (cq & 7) * 8;
        cpa16(sQ + (r * 72 + d) * 2, Qg + (size_t)r * DIM + d);
    }
    cpa_commit();

    auto issueK = [&](int kt) {
#pragma unroll
        for (int i = 0; i < 2; i++) {
            const int cc = t + i * 256;       // 512 chunks (64 x 8)
            const int r = cc >> 3, d = (cc & 7) * 8;
            cpa16(sK + (r * 72 + d) * 2, Kg + (size_t)(kt * 64 + r) * DIM + d);
        }
        cpa_commit();
    };
    auto issueV = [&](int kt) {
#pragma unroll
        for (int i = 0; i < 2; i++) {
            const int cc = t + i * 256;       // rows = dk, cols = seq chunk
            const int r = cc >> 3, d = (cc & 7) * 8;
            cpa16(sV + (r * 72 + d) * 2, Vtg + (size_t)r * SEQ + kt * 64 + d);
        }
        cpa_commit();
    };

    issueK(0);
    issueV(0);

    float m0 = -1e30f, m1 = -1e30f, l0 = 0.f, l1 = 0.f;
    float o[8][4];
#pragma unroll
    for (int di = 0; di < 8; di++)
#pragma unroll
        for (int r = 0; r < 4; r++) o[di][r] = 0.f;

    for (int kt = 0; kt < SEQ / 64; kt++) {
        asm volatile("cp.async.wait_group 0;");
        __syncthreads();

        // GEMM1: S[16q x 64k], 4 k16 steps over dk
        float s[8][4];
#pragma unroll
        for (int ni = 0; ni < 8; ni++)
#pragma unroll
            for (int r = 0; r < 4; r++) s[ni][r] = 0.f;
#pragma unroll
        for (int ks = 0; ks < 4; ks++) {
            const int ko = ks * 16;
            unsigned a0, a1, a2, a3;
            ldsm_x4(a0, a1, a2, a3, sQ + (qw * 72 + ko) * 2 + offA);
            unsigned bfr[8][2];
#pragma unroll
            for (int j = 0; j < 4; j++)
                ldsm_x4(bfr[2 * j][0], bfr[2 * j][1], bfr[2 * j + 1][0], bfr[2 * j + 1][1],
                        sK + ((j * 16) * 72 + ko) * 2 + offB);
#pragma unroll
            for (int ni = 0; ni < 8; ni++)
                mma_f16(s[ni], a0, a1, a2, a3, bfr[ni][0], bfr[ni][1]);
        }
        __syncthreads();                  // all warps done reading Ks
        if (kt + 1 < SEQ / 64) issueK(kt + 1);

        // Online softmax in registers
        float mx0 = -1e30f, mx1 = -1e30f;
#pragma unroll
        for (int ni = 0; ni < 8; ni++) {
            mx0 = fmaxf(mx0, fmaxf(s[ni][0], s[ni][1]));
            mx1 = fmaxf(mx1, fmaxf(s[ni][2], s[ni][3]));
        }
        mx0 = fmaxf(mx0, __shfl_xor_sync(0xffffffffu, mx0, 1));
        mx0 = fmaxf(mx0, __shfl_xor_sync(0xffffffffu, mx0, 2));
        mx1 = fmaxf(mx1, __shfl_xor_sync(0xffffffffu, mx1, 1));
        mx1 = fmaxf(mx1, __shfl_xor_sync(0xffffffffu, mx1, 2));
        const float mn0 = fmaxf(m0, mx0), mn1 = fmaxf(m1, mx1);
        const float al0 = __expf(m0 - mn0), al1 = __expf(m1 - mn1);
        m0 = mn0; m1 = mn1;
        float rs0 = 0.f, rs1 = 0.f;
#pragma unroll
        for (int ni = 0; ni < 8; ni++) {
            s[ni][0] = __expf(s[ni][0] - mn0);
            s[ni][1] = __expf(s[ni][1] - mn0);
            s[ni][2] = __expf(s[ni][2] - mn1);
            s[ni][3] = __expf(s[ni][3] - mn1);
            rs0 += s[ni][0] + s[ni][1];
            rs1 += s[ni][2] + s[ni][3];
        }
        rs0 += __shfl_xor_sync(0xffffffffu, rs0, 1);
        rs0 += __shfl_xor_sync(0xffffffffu, rs0, 2);
        rs1 += __shfl_xor_sync(0xffffffffu, rs1, 1);
        rs1 += __shfl_xor_sync(0xffffffffu, rs1, 2);
        l0 = l0 * al0 + rs0;
        l1 = l1 * al1 + rs1;

        // Pack P into registers: GEMM1 c-frag (row, 2gc..2gc+1) == GEMM2 a-frag
        unsigned pl[8], ph[8];
#pragma unroll
        for (int ni = 0; ni < 8; ni++) {
            pl[ni] = f2h2(s[ni][0], s[ni][1]);
            ph[ni] = f2h2(s[ni][2], s[ni][3]);
        }
#pragma unroll
        for (int di = 0; di < 8; di++) {
            o[di][0] *= al0; o[di][1] *= al0;
            o[di][2] *= al1; o[di][3] *= al1;
        }

        // GEMM2: O[16q x 64dk] += P @ V ; A from registers, B from Vs (dk-major)
#pragma unroll
        for (int ks = 0; ks < 4; ks++) {
            const int ko = ks * 16;
            const unsigned a0 = pl[2 * ks];
            const unsigned a1 = ph[2 * ks];
            const unsigned a2 = pl[2 * ks + 1];
            const unsigned a3 = ph[2 * ks + 1];
            unsigned bfr[8][2];
#pragma unroll
            for (int j = 0; j < 4; j++)
                ldsm_x4(bfr[2 * j][0], bfr[2 * j][1], bfr[2 * j + 1][0], bfr[2 * j + 1][1],
                        sV + ((j * 16) * 72 + ko) * 2 + offB);
#pragma unroll
            for (int di = 0; di < 8; di++)
                mma_f16(o[di], a0, a1, a2, a3, bfr[di][0], bfr[di][1]);
        }
        __syncthreads();                  // all warps done reading Vs
        if (kt + 1 < SEQ / 64) issueV(kt + 1);
    }

    // Epilogue: normalize, store ctx as fp16 (half2 per n-pair)
    const float i0 = 1.f / l0, i1 = 1.f / l1;
    const size_t r0 = (size_t)(b * SEQ + q0 + qw + gr) * DIM + h * DKH;
    const size_t r1 = (size_t)(b * SEQ + q0 + qw + gr + 8) * DIM + h * DKH;
#pragma unroll
    for (int di = 0; di < 8; di++) {
        const int col = di * 8 + 2 * gc;
        *(unsigned*)&O[r0 + col] = f2h2(o[di][0] * i0, o[di][1] * i0);
        *(unsigned*)&O[r1 + col] = f2h2(o[di][2] * i1, o[di][3] * i1);
    }
}

// ---------------------------------------------------------------------------
// Launch
// ---------------------------------------------------------------------------
extern "C" void kernel_launch(void* const* d_in, const int* in_sizes, int n_in,
                              void* d_out, int out_size) {
    const float* query  = (const float*)d_in[0];
    const float* key_in = (const float*)d_in[1];
    const float* value  = (const float*)d_in[2];
    const float* phys   = (const float*)d_in[3];
    const float* bq     = (const float*)d_in[5];
    const float* bk     = (const float*)d_in[7];
    const float* bv     = (const float*)d_in[9];
    const float* bo     = (const float*)d_in[11];
    const float* Pw     = (const float*)d_in[12];
    const float* pb     = (const float*)d_in[13];
    float* out          = (float*)d_out;

    __half *pQ, *pK, *pV, *pVt, *pC, *hA0, *hA1, *hA2, *hW;
    cudaGetSymbolAddress((void**)&pQ,  g_Qh);
    cudaGetSymbolAddress((void**)&pK,  g_Kh);
    cudaGetSymbolAddress((void**)&pV,  g_Vh);
    cudaGetSymbolAddress((void**)&pVt, g_Vt);
    cudaGetSymbolAddress((void**)&pC,  g_Ch);
    cudaGetSymbolAddress((void**)&hA0, g_hA0);
    cudaGetSymbolAddress((void**)&hA1, g_hA1);
    cudaGetSymbolAddress((void**)&hA2, g_hA2);
    cudaGetSymbolAddress((void**)&hW,  g_hWt);

    cudaFuncSetAttribute(sgemm_f16, cudaFuncAttributeMaxDynamicSharedMemorySize,
                         H_SMEM_BYTES);
    cudaFuncSetAttribute(attn_f16, cudaFuncAttributeMaxDynamicSharedMemorySize,
                         A_SMEM_BYTES);

    // Pre-convert inputs (fp16) and weights (transpose + fp16)
    cvt3_kernel<<<dim3(NELEM / 1024, 3), 256>>>(query, key_in, value, hA0, hA1, hA2);
    cvtWT_kernel<<<dim3(32, 32, 4), dim3(32, 8)>>>(
        (const float*)d_in[4], (const float*)d_in[6], (const float*)d_in[8],
        (const float*)d_in[10], hW);

    dim3 gg(DIM / 256, MROWS / 128);   // (4, 32)
    sgemm_f16<<<gg, 256, H_SMEM_BYTES>>>(hA0, hW + 0 * WELEM, bq, pQ, 1, 0.125f,
                                         nullptr, nullptr, nullptr);
    sgemm_f16<<<gg, 256, H_SMEM_BYTES>>>(hA1, hW + 1 * WELEM, bk, pK, 1, 1.0f,
                                         phys, Pw, pb);
    sgemm_f16<<<gg, 256, H_SMEM_BYTES>>>(hA2, hW + 2 * WELEM, bv, pV, 1, 1.0f,
                                         nullptr, nullptr, nullptr);

    // V -> V^T (dk-major) for attention GEMM2 B-operand
    transposeV_kernel<<<dim3(SEQ / 32, DIM / 32, 2), dim3(32, 8)>>>(pV, pVt);

    dim3 ga(SEQ / 128, HEADS, 2);      // (16, 16, 2)
    attn_f16<<<ga, 256, A_SMEM_BYTES>>>(pQ, pK, pVt, pC);

    sgemm_f16<<<gg, 256, H_SMEM_BYTES>>>(pC, hW + 3 * WELEM, bo, out, 0, 1.0f,
                                         nullptr, nullptr, nullptr);
}

// round 15
// speedup vs baseline: 11.4476x; 1.0182x over previous
#include <cuda_runtime.h>
#include <cuda_fp16.h>
#include <cstdint>

#define MROWS 4096
#define DIM   1024
#define HEADS 16
#define DKH   64
#define SEQ   2048
#define NELEM (MROWS * DIM)
#define WELEM (DIM * DIM)

// ---------------------------------------------------------------------------
// Scratch (device globals; no allocation allowed)
// ---------------------------------------------------------------------------
__device__ __half g_Qh[NELEM];      // Q proj (pre-scaled 0.125)
__device__ __half g_Kh[NELEM];      // K proj (+physics fold)
__device__ __half g_Vh[NELEM];      // V proj [m][n]
__device__ __half g_Vt[NELEM];      // V transposed: [(b*16+h)*64+dk][s]
__device__ __half g_Ch[NELEM];      // attention ctx
__device__ __half g_hA0[NELEM];     // query  (fp16)
__device__ __half g_hA1[NELEM];     // key_in (fp16)
__device__ __half g_hA2[NELEM];     // value  (fp16)
__device__ __half g_hWt[4 * WELEM]; // W^T [N][K] fp16

// ---------------------------------------------------------------------------
// Helpers
// ---------------------------------------------------------------------------
__device__ __forceinline__ unsigned f2h2(float x, float y) {
    __half2 h = __floats2half2_rn(x, y);
    return *(unsigned*)&h;
}
__device__ __forceinline__ void mma_f16(float c[4], unsigned a0, unsigned a1,
                                        unsigned a2, unsigned a3,
                                        unsigned b0, unsigned b1) {
    asm volatile(
        "mma.sync.aligned.m16n8k16.row.col.f32.f16.f16.f32 "
        "{%0,%1,%2,%3}, {%4,%5,%6,%7}, {%8,%9}, {%0,%1,%2,%3};"
        : "+f"(c[0]), "+f"(c[1]), "+f"(c[2]), "+f"(c[3])
        : "r"(a0), "r"(a1), "r"(a2), "r"(a3), "r"(b0), "r"(b1));
}
__device__ __forceinline__ void ldsm_x4(unsigned& r0, unsigned& r1, unsigned& r2,
                                        unsigned& r3, unsigned saddr) {
    asm volatile("ldmatrix.sync.aligned.m8n8.x4.shared.b16 {%0,%1,%2,%3}, [%4];"
                 : "=r"(r0), "=r"(r1), "=r"(r2), "=r"(r3) : "r"(saddr));
}
__device__ __forceinline__ void cpa16(unsigned saddr, const void* g) {
    asm volatile("cp.async.cg.shared.global [%0], [%1], 16;" :: "r"(saddr), "l"(g));
}
__device__ __forceinline__ void cpa_commit() {
    asm volatile("cp.async.commit_group;");
}

// ---------------------------------------------------------------------------
// fp32 -> fp16 pre-conversion (3 inputs) and weight transpose+fp16
// ---------------------------------------------------------------------------
__global__ void cvt3_kernel(const float* __restrict__ a, const float* __restrict__ b,
                            const float* __restrict__ c, __half* __restrict__ oa,
                            __half* __restrict__ ob, __half* __restrict__ oc) {
    const float* s = (blockIdx.y == 0) ? a : (blockIdx.y == 1) ? b : c;
    __half* d      = (blockIdx.y == 0) ? oa : (blockIdx.y == 1) ? ob : oc;
    const int i = (blockIdx.x * 256 + threadIdx.x) * 4;
    float4 v = *(const float4*)(s + i);
    uint2 o;
    o.x = f2h2(v.x, v.y);
    o.y = f2h2(v.z, v.w);
    *(uint2*)(d + i) = o;
}
// dst[n*K + k] = half(w[k*N + n])
__global__ void cvtWT_kernel(const float* __restrict__ w0, const float* __restrict__ w1,
                             const float* __restrict__ w2, const float* __restrict__ w3,
                             __half* __restrict__ dst) {
    __shared__ float tile[32][33];
    const float* s = (blockIdx.z == 0) ? w0 : (blockIdx.z == 1) ? w1
                     : (blockIdx.z == 2) ? w2 : w3;
    __half* d = dst + (size_t)blockIdx.z * WELEM;
    const int tx = threadIdx.x, ty = threadIdx.y;   // 32 x 8
    const int k0 = blockIdx.y * 32, n0 = blockIdx.x * 32;
#pragma unroll
    for (int j = 0; j < 32; j += 8)
        tile[ty + j][tx] = s[(size_t)(k0 + ty + j) * DIM + n0 + tx];
    __syncthreads();
#pragma unroll
    for (int j = 0; j < 32; j += 8)
        d[(size_t)(n0 + ty + j) * DIM + k0 + tx] = __float2half_rn(tile[tx][ty + j]);
}
// Vt[(b*1024 + n)][s] = Vh[(b*2048+s)][n]
__global__ void transposeV_kernel(const __half* __restrict__ src, __half* __restrict__ dst) {
    __shared__ __half tile[32][34];
    const int b = blockIdx.z;
    const int s0 = blockIdx.x * 32, n0 = blockIdx.y * 32;
    const int tx = threadIdx.x, ty = threadIdx.y;   // 32 x 8
#pragma unroll
    for (int j = 0; j < 32; j += 8)
        tile[ty + j][tx] = src[(size_t)(b * SEQ + s0 + ty + j) * DIM + n0 + tx];
    __syncthreads();
#pragma unroll
    for (int j = 0; j < 32; j += 8)
        dst[(size_t)(b * DIM + n0 + ty + j) * SEQ + s0 + tx] = tile[tx][ty + j];
}

// ---------------------------------------------------------------------------
// FP16 GEMM: C[4096,1024] = A[4096,1024] @ Wt[N][K]^T + bias (+ physics)
// CTA 128x128, BK=32, 4-stage cp.async, 8 warps (2m x 4n), warp tile 64x32,
// 2 CTAs/SM (4 warps/SMSP for latency hiding). ldmatrix fragment loads.
// As[m][k] / Bs[n][k] stride 40 halfs (conflict-free for LDSM, proven R13).
// ---------------------------------------------------------------------------
#define H_AS_STG 5120               // 128*40 halfs
#define H_BS_STG 5120               // 128*40 halfs
#define H_NST    4
#define H_SMEM_BYTES ((H_AS_STG + H_BS_STG) * H_NST * 2)   // 81920
#define H_KIT 32

__global__ __launch_bounds__(256, 2)
void sgemm_f16(const __half* __restrict__ A, const __half* __restrict__ Wt,
               const float* __restrict__ bias, void* __restrict__ Cout,
               int out_half, float oscale,
               const float* __restrict__ phys, const float* __restrict__ Pw,
               const float* __restrict__ pb) {
    extern __shared__ __half sh[];
    __half* AsB = sh;                          // [4][5120]
    __half* BsB = sh + H_NST * H_AS_STG;       // [4][5120]
    const unsigned sA = (unsigned)__cvta_generic_to_shared(AsB);
    const unsigned sB = (unsigned)__cvta_generic_to_shared(BsB);

    const int t    = threadIdx.x;
    const int w    = t >> 5;
    const int lane = t & 31;
    const int wm   = w >> 2;          // 0..1
    const int wn   = w & 3;           // 0..3
    const int gr   = lane >> 2;       // 0..7
    const int gc   = lane & 3;        // 0..3
    const int n0   = blockIdx.x * 128;
    const int m0   = blockIdx.y * 128;

    // ldmatrix per-lane offsets (bytes), stride 40 halfs:
    const unsigned offA = ((((lane & 7) + ((lane & 8) ? 8 : 0)) * 40) +
                           ((lane & 16) ? 8 : 0)) * 2;
    const unsigned offB = (((((lane >> 4) * 8) + (lane & 7)) * 40) +
                           ((lane & 8) ? 8 : 0)) * 2;

    float c[4][4][4];
#pragma unroll
    for (int mi = 0; mi < 4; mi++)
#pragma unroll
        for (int ni = 0; ni < 4; ni++)
#pragma unroll
            for (int r = 0; r < 4; r++) c[mi][ni][r] = 0.f;

    // one stage: A 128x32 halfs (512 x16B chunks, 2/thr), B 128x32 (512, 2/thr)
    auto issue = [&](int stage, int k0) {
#pragma unroll
        for (int i = 0; i < 2; i++) {
            const int ca = t + i * 256;
            const int ar = ca >> 2, ac = (ca & 3) * 8;
            cpa16(sA + (stage * H_AS_STG + ar * 40 + ac) * 2,
                  A + (size_t)(m0 + ar) * DIM + k0 + ac);
            cpa16(sB + (stage * H_BS_STG + ar * 40 + ac) * 2,
                  Wt + (size_t)(n0 + ar) * DIM + k0 + ac);
        }
        cpa_commit();
    };

    issue(0, 0);
    issue(1, 32);
    issue(2, 64);

    for (int it = 0; it < H_KIT; it++) {
        if (it + 3 < H_KIT) {
            issue((it + 3) & 3, (it + 3) * 32);
            asm volatile("cp.async.wait_group 3;");
        } else if (it == H_KIT - 3) {
            asm volatile("cp.async.wait_group 2;");
        } else if (it == H_KIT - 2) {
            asm volatile("cp.async.wait_group 1;");
        } else {
            asm volatile("cp.async.wait_group 0;");
        }
        __syncthreads();

        const unsigned aBase = sA + (it & 3) * H_AS_STG * 2;
        const unsigned bBase = sB + (it & 3) * H_BS_STG * 2;
#pragma unroll
        for (int ks = 0; ks < 2; ks++) {
            const int ko = ks * 16;
            unsigned a[4][4];
#pragma unroll
            for (int mi = 0; mi < 4; mi++)
                ldsm_x4(a[mi][0], a[mi][1], a[mi][2], a[mi][3],
                        aBase + ((wm * 64 + mi * 16) * 40 + ko) * 2 + offA);
            unsigned b[4][2];
#pragma unroll
            for (int j = 0; j < 2; j++)
                ldsm_x4(b[2 * j][0], b[2 * j][1], b[2 * j + 1][0], b[2 * j + 1][1],
                        bBase + ((wn * 32 + j * 16) * 40 + ko) * 2 + offB);
#pragma unroll
            for (int mi = 0; mi < 4; mi++)
#pragma unroll
                for (int ni = 0; ni < 4; ni++)
                    mma_f16(c[mi][ni], a[mi][0], a[mi][1], a[mi][2], a[mi][3],
                            b[ni][0], b[ni][1]);
        }
        __syncthreads();
    }

    // Epilogue: bias (+ physics fold for K projection)
    const float pbv = phys ? pb[0] : 0.f;
#pragma unroll
    for (int mi = 0; mi < 4; mi++) {
#pragma unroll
        for (int h2 = 0; h2 < 2; h2++) {
            const int m = m0 + wm * 64 + mi * 16 + gr + h2 * 8;
            float p0 = 0.f, p1 = 0.f, p2 = 0.f;
            int jjb = 0;
            if (phys) {
                const int bi = m >> 11;
                const int sq = m & 2047;
                const float* ph = phys + (size_t)((bi << 7) + (sq >> 4)) * 3;
                p0 = ph[0]; p1 = ph[1]; p2 = ph[2];
                jjb = (sq & 15) << 6;
            }
#pragma unroll
            for (int ni = 0; ni < 4; ni++) {
                const int n = n0 + wn * 32 + ni * 8 + 2 * gc;
                float v0 = c[mi][ni][h2 * 2 + 0] + bias[n];
                float v1 = c[mi][ni][h2 * 2 + 1] + bias[n + 1];
                if (phys) {
                    const int j0 = jjb + (n & 63);
                    v0 += pbv * (p0 * Pw[j0]     + p1 * Pw[1024 + j0]     + p2 * Pw[2048 + j0]);
                    v1 += pbv * (p0 * Pw[j0 + 1] + p1 * Pw[1024 + j0 + 1] + p2 * Pw[2048 + j0 + 1]);
                }
                if (out_half) {
                    *(unsigned*)&((__half*)Cout)[(size_t)m * DIM + n] =
                        f2h2(v0 * oscale, v1 * oscale);
                } else {
                    *(float2*)&((float*)Cout)[(size_t)m * DIM + n] = make_float2(v0, v1);
                }
            }
        }
    }
}

// ---------------------------------------------------------------------------
// FP16 flash attention (unchanged from R13, ~530 TF/s).
// CTA = (b, h, 128 q rows); 8 warps, 16 q rows each; P stays in registers.
// SMEM (halfs, stride 72): Qs[128][72] | Ks[64][72] | Vs(dk-major)[64][72]
// ---------------------------------------------------------------------------
#define AQ_OFF 0
#define AK_OFF 9216
#define AV_OFF 13824
#define A_SMEM_BYTES ((13824 + 64 * 72) * 2)   // 36864

__global__ __launch_bounds__(256, 2)
void attn_f16(const __half* __restrict__ Q, const __half* __restrict__ K,
              const __half* __restrict__ Vt, __half* __restrict__ O) {
    extern __shared__ __half sm_h[];
    __half* Qs = sm_h + AQ_OFF;
    __half* Ks = sm_h + AK_OFF;
    __half* Vs = sm_h + AV_OFF;
    const unsigned sQ = (unsigned)__cvta_generic_to_shared(Qs);
    const unsigned sK = (unsigned)__cvta_generic_to_shared(Ks);
    const unsigned sV = (unsigned)__cvta_generic_to_shared(Vs);

    const int t    = threadIdx.x;
    const int w    = t >> 5;
    const int lane = t & 31;
    const int gr   = lane >> 2;
    const int gc   = lane & 3;
    const int qw   = w * 16;
    const int qb   = blockIdx.x;
    const int h    = blockIdx.y;
    const int b    = blockIdx.z;
    const int q0   = qb * 128;

    // ldmatrix per-lane offsets (bytes), stride 72 halfs
    const unsigned offA = ((((lane & 7) + ((lane & 8) ? 8 : 0)) * 72) +
                           ((lane & 16) ? 8 : 0)) * 2;
    const unsigned offB = (((((lane >> 4) * 8) + (lane & 7)) * 72) +
                           ((lane & 8) ? 8 : 0)) * 2;

    const __half* Qg  = Q  + ((size_t)(b * SEQ + q0)) * DIM + h * DKH;
    const __half* Kg  = K  + ((size_t)b * SEQ) * DIM + h * DKH;
    const __half* Vtg = Vt + (size_t)(b * DIM + h * DKH) * SEQ;

    // Q tile: 128 x 64 halfs = 1024 chunks (4/thread)
#pragma unroll
    for (int i = 0; i < 4; i++) {
        const int cq = t + i * 256;
        const int r = cq >> 3, d = (cq & 7) * 8;
        cpa16(sQ + (r * 72 + d) * 2, Qg + (size_t)r * DIM + d);
    }
    cpa_commit();

    auto issueK = [&](int kt) {
#pragma unroll
        for (int i = 0; i < 2; i++) {
            const int cc = t + i * 256;       // 512 chunks (64 x 8)
            const int r = cc >> 3, d = (cc & 7) * 8;
            cpa16(sK + (r * 72 + d) * 2, Kg + (size_t)(kt * 64 + r) * DIM + d);
        }
        cpa_commit();
    };
    auto issueV = [&](int kt) {
#pragma unroll
        for (int i = 0; i < 2; i++) {
            const int cc = t + i * 256;       // rows = dk, cols = seq chunk
            const int r = cc >> 3, d = (cc & 7) * 8;
            cpa16(sV + (r * 72 + d) * 2, Vtg + (size_t)r * SEQ + kt * 64 + d);
        }
        cpa_commit();
    };

    issueK(0);
    issueV(0);

    float m0 = -1e30f, m1 = -1e30f, l0 = 0.f, l1 = 0.f;
    float o[8][4];
#pragma unroll
    for (int di = 0; di < 8; di++)
#pragma unroll
        for (int r = 0; r < 4; r++) o[di][r] = 0.f;

    for (int kt = 0; kt < SEQ / 64; kt++) {
        asm volatile("cp.async.wait_group 0;");
        __syncthreads();

        // GEMM1: S[16q x 64k], 4 k16 steps over dk
        float s[8][4];
#pragma unroll
        for (int ni = 0; ni < 8; ni++)
#pragma unroll
            for (int r = 0; r < 4; r++) s[ni][r] = 0.f;
#pragma unroll
        for (int ks = 0; ks < 4; ks++) {
            const int ko = ks * 16;
            unsigned a0, a1, a2, a3;
            ldsm_x4(a0, a1, a2, a3, sQ + (qw * 72 + ko) * 2 + offA);
            unsigned bfr[8][2];
#pragma unroll
            for (int j = 0; j < 4; j++)
                ldsm_x4(bfr[2 * j][0], bfr[2 * j][1], bfr[2 * j + 1][0], bfr[2 * j + 1][1],
                        sK + ((j * 16) * 72 + ko) * 2 + offB);
#pragma unroll
            for (int ni = 0; ni < 8; ni++)
                mma_f16(s[ni], a0, a1, a2, a3, bfr[ni][0], bfr[ni][1]);
        }
        __syncthreads();                  // all warps done reading Ks
        if (kt + 1 < SEQ / 64) issueK(kt + 1);

        // Online softmax in registers
        float mx0 = -1e30f, mx1 = -1e30f;
#pragma unroll
        for (int ni = 0; ni < 8; ni++) {
            mx0 = fmaxf(mx0, fmaxf(s[ni][0], s[ni][1]));
            mx1 = fmaxf(mx1, fmaxf(s[ni][2], s[ni][3]));
        }
        mx0 = fmaxf(mx0, __shfl_xor_sync(0xffffffffu, mx0, 1));
        mx0 = fmaxf(mx0, __shfl_xor_sync(0xffffffffu, mx0, 2));
        mx1 = fmaxf(mx1, __shfl_xor_sync(0xffffffffu, mx1, 1));
        mx1 = fmaxf(mx1, __shfl_xor_sync(0xffffffffu, mx1, 2));
        const float mn0 = fmaxf(m0, mx0), mn1 = fmaxf(m1, mx1);
        const float al0 = __expf(m0 - mn0), al1 = __expf(m1 - mn1);
        m0 = mn0; m1 = mn1;
        float rs0 = 0.f, rs1 = 0.f;
#pragma unroll
        for (int ni = 0; ni < 8; ni++) {
            s[ni][0] = __expf(s[ni][0] - mn0);
            s[ni][1] = __expf(s[ni][1] - mn0);
            s[ni][2] = __expf(s[ni][2] - mn1);
            s[ni][3] = __expf(s[ni][3] - mn1);
            rs0 += s[ni][0] + s[ni][1];
            rs1 += s[ni][2] + s[ni][3];
        }
        rs0 += __shfl_xor_sync(0xffffffffu, rs0, 1);
        rs0 += __shfl_xor_sync(0xffffffffu, rs0, 2);
        rs1 += __shfl_xor_sync(0xffffffffu, rs1, 1);
        rs1 += __shfl_xor_sync(0xffffffffu, rs1, 2);
        l0 = l0 * al0 + rs0;
        l1 = l1 * al1 + rs1;

        // Pack P into registers: GEMM1 c-frag (row, 2gc..2gc+1) == GEMM2 a-frag
        unsigned pl[8], ph[8];
#pragma unroll
        for (int ni = 0; ni < 8; ni++) {
            pl[ni] = f2h2(s[ni][0], s[ni][1]);
            ph[ni] = f2h2(s[ni][2], s[ni][3]);
        }
#pragma unroll
        for (int di = 0; di < 8; di++) {
            o[di][0] *= al0; o[di][1] *= al0;
            o[di][2] *= al1; o[di][3] *= al1;
        }

        // GEMM2: O[16q x 64dk] += P @ V ; A from registers, B from Vs (dk-major)
#pragma unroll
        for (int ks = 0; ks < 4; ks++) {
            const int ko = ks * 16;
            const unsigned a0 = pl[2 * ks];
            const unsigned a1 = ph[2 * ks];
            const unsigned a2 = pl[2 * ks + 1];
            const unsigned a3 = ph[2 * ks + 1];
            unsigned bfr[8][2];
#pragma unroll
            for (int j = 0; j < 4; j++)
                ldsm_x4(bfr[2 * j][0], bfr[2 * j][1], bfr[2 * j + 1][0], bfr[2 * j + 1][1],
                        sV + ((j * 16) * 72 + ko) * 2 + offB);
#pragma unroll
            for (int di = 0; di < 8; di++)
                mma_f16(o[di], a0, a1, a2, a3, bfr[di][0], bfr[di][1]);
        }
        __syncthreads();                  // all warps done reading Vs
        if (kt + 1 < SEQ / 64) issueV(kt + 1);
    }

    // Epilogue: normalize, store ctx as fp16 (half2 per n-pair)
    const float i0 = 1.f / l0, i1 = 1.f / l1;
    const size_t r0 = (size_t)(b * SEQ + q0 + qw + gr) * DIM + h * DKH;
    const size_t r1 = (size_t)(b * SEQ + q0 + qw + gr + 8) * DIM + h * DKH;
#pragma unroll
    for (int di = 0; di < 8; di++) {
        const int col = di * 8 + 2 * gc;
        *(unsigned*)&O[r0 + col] = f2h2(o[di][0] * i0, o[di][1] * i0);
        *(unsigned*)&O[r1 + col] = f2h2(o[di][2] * i1, o[di][3] * i1);
    }
}

// ---------------------------------------------------------------------------
// Launch
// ---------------------------------------------------------------------------
extern "C" void kernel_launch(void* const* d_in, const int* in_sizes, int n_in,
                              void* d_out, int out_size) {
    const float* query  = (const float*)d_in[0];
    const float* key_in = (const float*)d_in[1];
    const float* value  = (const float*)d_in[2];
    const float* phys   = (const float*)d_in[3];
    const float* bq     = (const float*)d_in[5];
    const float* bk     = (const float*)d_in[7];
    const float* bv     = (const float*)d_in[9];
    const float* bo     = (const float*)d_in[11];
    const float* Pw     = (const float*)d_in[12];
    const float* pb     = (const float*)d_in[13];
    float* out          = (float*)d_out;

    __half *pQ, *pK, *pV, *pVt, *pC, *hA0, *hA1, *hA2, *hW;
    cudaGetSymbolAddress((void**)&pQ,  g_Qh);
    cudaGetSymbolAddress((void**)&pK,  g_Kh);
    cudaGetSymbolAddress((void**)&pV,  g_Vh);
    cudaGetSymbolAddress((void**)&pVt, g_Vt);
    cudaGetSymbolAddress((void**)&pC,  g_Ch);
    cudaGetSymbolAddress((void**)&hA0, g_hA0);
    cudaGetSymbolAddress((void**)&hA1, g_hA1);
    cudaGetSymbolAddress((void**)&hA2, g_hA2);
    cudaGetSymbolAddress((void**)&hW,  g_hWt);

    cudaFuncSetAttribute(sgemm_f16, cudaFuncAttributeMaxDynamicSharedMemorySize,
                         H_SMEM_BYTES);
    cudaFuncSetAttribute(attn_f16, cudaFuncAttributeMaxDynamicSharedMemorySize,
                         A_SMEM_BYTES);

    // Pre-convert inputs (fp16) and weights (transpose + fp16)
    cvt3_kernel<<<dim3(NELEM / 1024, 3), 256>>>(query, key_in, value, hA0, hA1, hA2);
    cvtWT_kernel<<<dim3(32, 32, 4), dim3(32, 8)>>>(
        (const float*)d_in[4], (const float*)d_in[6], (const float*)d_in[8],
        (const float*)d_in[10], hW);

    dim3 gg(DIM / 128, MROWS / 128);   // (8, 32) = 256 CTAs, 2/SM
    sgemm_f16<<<gg, 256, H_SMEM_BYTES>>>(hA0, hW + 0 * WELEM, bq, pQ, 1, 0.125f,
                                         nullptr, nullptr, nullptr);
    sgemm_f16<<<gg, 256, H_SMEM_BYTES>>>(hA1, hW + 1 * WELEM, bk, pK, 1, 1.0f,
                                         phys, Pw, pb);
    sgemm_f16<<<gg, 256, H_SMEM_BYTES>>>(hA2, hW + 2 * WELEM, bv, pV, 1, 1.0f,
                                         nullptr, nullptr, nullptr);

    // V -> V^T (dk-major) for attention GEMM2 B-operand
    transposeV_kernel<<<dim3(SEQ / 32, DIM / 32, 2), dim3(32, 8)>>>(pV, pVt);

    dim3 ga(SEQ / 128, HEADS, 2);      // (16, 16, 2)
    attn_f16<<<ga, 256, A_SMEM_BYTES>>>(pQ, pK, pVt, pC);

    sgemm_f16<<<gg, 256, H_SMEM_BYTES>>>(pC, hW + 3 * WELEM, bo, out, 0, 1.0f,
                                         nullptr, nullptr, nullptr);
}

// round 17
// speedup vs baseline: 12.1180x; 1.0586x over previous
#include <cuda_runtime.h>
#include <cuda_fp16.h>
#include <cstdint>

#define MROWS 4096
#define DIM   1024
#define HEADS 16
#define DKH   64
#define SEQ   2048
#define NELEM (MROWS * DIM)
#define WELEM (DIM * DIM)

// ---------------------------------------------------------------------------
// Scratch (device globals; no allocation allowed)
// ---------------------------------------------------------------------------
__device__ __half g_Qh[NELEM];      // Q proj (pre-scaled 0.125)
__device__ __half g_Kh[NELEM];      // K proj (+physics fold)
__device__ __half g_Vh[NELEM];      // V proj [m][n]
__device__ __half g_Vt[NELEM];      // V transposed: [(b*16+h)*64+dk][s]
__device__ __half g_Ch[NELEM];      // attention ctx
__device__ __half g_hA0[NELEM];     // query  (fp16)
__device__ __half g_hA1[NELEM];     // key_in (fp16)
__device__ __half g_hA2[NELEM];     // value  (fp16)
__device__ __half g_hWt[4 * WELEM]; // W^T [N][K] fp16

// ---------------------------------------------------------------------------
// Helpers
// ---------------------------------------------------------------------------
__device__ __forceinline__ unsigned f2h2(float x, float y) {
    __half2 h = __floats2half2_rn(x, y);
    return *(unsigned*)&h;
}
__device__ __forceinline__ void mma_f16(float c[4], unsigned a0, unsigned a1,
                                        unsigned a2, unsigned a3,
                                        unsigned b0, unsigned b1) {
    asm volatile(
        "mma.sync.aligned.m16n8k16.row.col.f32.f16.f16.f32 "
        "{%0,%1,%2,%3}, {%4,%5,%6,%7}, {%8,%9}, {%0,%1,%2,%3};"
        : "+f"(c[0]), "+f"(c[1]), "+f"(c[2]), "+f"(c[3])
        : "r"(a0), "r"(a1), "r"(a2), "r"(a3), "r"(b0), "r"(b1));
}
__device__ __forceinline__ void ldsm_x4(unsigned& r0, unsigned& r1, unsigned& r2,
                                        unsigned& r3, unsigned saddr) {
    asm volatile("ldmatrix.sync.aligned.m8n8.x4.shared.b16 {%0,%1,%2,%3}, [%4];"
                 : "=r"(r0), "=r"(r1), "=r"(r2), "=r"(r3) : "r"(saddr));
}
__device__ __forceinline__ void cpa16(unsigned saddr, const void* g) {
    asm volatile("cp.async.cg.shared.global [%0], [%1], 16;" :: "r"(saddr), "l"(g));
}
__device__ __forceinline__ void cpa_commit() {
    asm volatile("cp.async.commit_group;");
}

// ---------------------------------------------------------------------------
// fp32 -> fp16 pre-conversion (3 inputs) and weight transpose+fp16
// ---------------------------------------------------------------------------
__global__ void cvt3_kernel(const float* __restrict__ a, const float* __restrict__ b,
                            const float* __restrict__ c, __half* __restrict__ oa,
                            __half* __restrict__ ob, __half* __restrict__ oc) {
    const float* s = (blockIdx.y == 0) ? a : (blockIdx.y == 1) ? b : c;
    __half* d      = (blockIdx.y == 0) ? oa : (blockIdx.y == 1) ? ob : oc;
    const int i = (blockIdx.x * 256 + threadIdx.x) * 4;
    float4 v = *(const float4*)(s + i);
    uint2 o;
    o.x = f2h2(v.x, v.y);
    o.y = f2h2(v.z, v.w);
    *(uint2*)(d + i) = o;
}
// dst[n*K + k] = half(w[k*N + n])
__global__ void cvtWT_kernel(const float* __restrict__ w0, const float* __restrict__ w1,
                             const float* __restrict__ w2, const float* __restrict__ w3,
                             __half* __restrict__ dst) {
    __shared__ float tile[32][33];
    const float* s = (blockIdx.z == 0) ? w0 : (blockIdx.z == 1) ? w1
                     : (blockIdx.z == 2) ? w2 : w3;
    __half* d = dst + (size_t)blockIdx.z * WELEM;
    const int tx = threadIdx.x, ty = threadIdx.y;   // 32 x 8
    const int k0 = blockIdx.y * 32, n0 = blockIdx.x * 32;
#pragma unroll
    for (int j = 0; j < 32; j += 8)
        tile[ty + j][tx] = s[(size_t)(k0 + ty + j) * DIM + n0 + tx];
    __syncthreads();
#pragma unroll
    for (int j = 0; j < 32; j += 8)
        d[(size_t)(n0 + ty + j) * DIM + k0 + tx] = __float2half_rn(tile[tx][ty + j]);
}
// Vt[(b*1024 + n)][s] = Vh[(b*2048+s)][n]
__global__ void transposeV_kernel(const __half* __restrict__ src, __half* __restrict__ dst) {
    __shared__ __half tile[32][34];
    const int b = blockIdx.z;
    const int s0 = blockIdx.x * 32, n0 = blockIdx.y * 32;
    const int tx = threadIdx.x, ty = threadIdx.y;   // 32 x 8
#pragma unroll
    for (int j = 0; j < 32; j += 8)
        tile[ty + j][tx] = src[(size_t)(b * SEQ + s0 + ty + j) * DIM + n0 + tx];
    __syncthreads();
#pragma unroll
    for (int j = 0; j < 32; j += 8)
        dst[(size_t)(b * DIM + n0 + ty + j) * SEQ + s0 + tx] = tile[tx][ty + j];
}

// ---------------------------------------------------------------------------
// Batched FP16 GEMM: C_z[4096,1024] = A_z @ Wt_z^T + bias_z (+ physics on z==1)
// blockIdx.z selects the problem. CTA 128x128, BK=64 (4 x k16), 3-stage
// cp.async ring, 8 warps (2m x 4n), warp tile 64x32, ldmatrix loads,
// rows stride 72 halfs (attention-proven conflict-free).
// 16 epochs (vs 32) halve barrier/wait overhead per unit MMA.
// ---------------------------------------------------------------------------
#define G_AS_STG 9216               // 128*72 halfs (18432 B)
#define G_NST    3
#define G_SMEM_BYTES (G_AS_STG * 2 * G_NST * 2)   // 110592 B
#define G_KIT 16

__global__ __launch_bounds__(256, 2)
void gemm_f16_batched(const __half* __restrict__ A0, const __half* __restrict__ A1,
                      const __half* __restrict__ A2, const __half* __restrict__ Wb,
                      const float* __restrict__ b0, const float* __restrict__ b1,
                      const float* __restrict__ b2,
                      void* __restrict__ C0, void* __restrict__ C1,
                      void* __restrict__ C2,
                      int out_half, float oscale0,
                      const float* __restrict__ phys, const float* __restrict__ Pw,
                      const float* __restrict__ pb) {
    extern __shared__ __half sh[];
    __half* AsB = sh;                          // [3][9216]
    __half* BsB = sh + G_NST * G_AS_STG;       // [3][9216]
    const unsigned sA = (unsigned)__cvta_generic_to_shared(AsB);
    const unsigned sB = (unsigned)__cvta_generic_to_shared(BsB);

    const int z    = blockIdx.z;
    const __half* A  = (z == 0) ? A0 : (z == 1) ? A1 : A2;
    const __half* Wt = Wb + (size_t)z * WELEM;
    const float* bias = (z == 0) ? b0 : (z == 1) ? b1 : b2;
    void* Cout = (z == 0) ? C0 : (z == 1) ? C1 : C2;
    const float oscale = (z == 0) ? oscale0 : 1.0f;
    const bool do_phys = (z == 1) && (phys != nullptr);

    const int t    = threadIdx.x;
    const int w    = t >> 5;
    const int lane = t & 31;
    const int wm   = w >> 2;          // 0..1
    const int wn   = w & 3;           // 0..3
    const int gr   = lane >> 2;       // 0..7
    const int gc   = lane & 3;        // 0..3
    const int n0   = blockIdx.x * 128;
    const int m0   = blockIdx.y * 128;

    // ldmatrix per-lane offsets (bytes), stride 72 halfs (proven in attn):
    const unsigned offA = ((((lane & 7) + ((lane & 8) ? 8 : 0)) * 72) +
                           ((lane & 16) ? 8 : 0)) * 2;
    const unsigned offB = (((((lane >> 4) * 8) + (lane & 7)) * 72) +
                           ((lane & 8) ? 8 : 0)) * 2;

    float c[4][4][4];
#pragma unroll
    for (int mi = 0; mi < 4; mi++)
#pragma unroll
        for (int ni = 0; ni < 4; ni++)
#pragma unroll
            for (int r = 0; r < 4; r++) c[mi][ni][r] = 0.f;

    // one stage: A 128x64 halfs (1024 x16B chunks, 4/thr), B same
    auto issue = [&](int stage, int k0) {
#pragma unroll
        for (int i = 0; i < 4; i++) {
            const int ca = t + i * 256;
            const int ar = ca >> 3, ac = (ca & 7) * 8;
            cpa16(sA + (stage * G_AS_STG + ar * 72 + ac) * 2,
                  A + (size_t)(m0 + ar) * DIM + k0 + ac);
            cpa16(sB + (stage * G_AS_STG + ar * 72 + ac) * 2,
                  Wt + (size_t)(n0 + ar) * DIM + k0 + ac);
        }
        cpa_commit();
    };

    issue(0, 0);
    issue(1, 64);

    for (int it = 0; it < G_KIT; it++) {
        if (it + 2 < G_KIT) {
            issue((it + 2) % 3, (it + 2) * 64);
            asm volatile("cp.async.wait_group 2;");
        } else if (it == G_KIT - 2) {
            asm volatile("cp.async.wait_group 1;");
        } else {
            asm volatile("cp.async.wait_group 0;");
        }
        __syncthreads();

        const int st = it % 3;
        const unsigned aBase = sA + st * G_AS_STG * 2;
        const unsigned bBase = sB + st * G_AS_STG * 2;
#pragma unroll
        for (int ks = 0; ks < 4; ks++) {
            const int ko = ks * 16;
            unsigned a[4][4];
#pragma unroll
            for (int mi = 0; mi < 4; mi++)
                ldsm_x4(a[mi][0], a[mi][1], a[mi][2], a[mi][3],
                        aBase + ((wm * 64 + mi * 16) * 72 + ko) * 2 + offA);
            unsigned b[4][2];
#pragma unroll
            for (int j = 0; j < 2; j++)
                ldsm_x4(b[2 * j][0], b[2 * j][1], b[2 * j + 1][0], b[2 * j + 1][1],
                        bBase + ((wn * 32 + j * 16) * 72 + ko) * 2 + offB);
#pragma unroll
            for (int mi = 0; mi < 4; mi++)
#pragma unroll
                for (int ni = 0; ni < 4; ni++)
                    mma_f16(c[mi][ni], a[mi][0], a[mi][1], a[mi][2], a[mi][3],
                            b[ni][0], b[ni][1]);
        }
        __syncthreads();
    }

    // Epilogue: bias (+ physics fold for z==1)
    const float pbv = do_phys ? pb[0] : 0.f;
#pragma unroll
    for (int mi = 0; mi < 4; mi++) {
#pragma unroll
        for (int h2 = 0; h2 < 2; h2++) {
            const int m = m0 + wm * 64 + mi * 16 + gr + h2 * 8;
            float p0 = 0.f, p1 = 0.f, p2 = 0.f;
            int jjb = 0;
            if (do_phys) {
                const int bi = m >> 11;
                const int sq = m & 2047;
                const float* ph = phys + (size_t)((bi << 7) + (sq >> 4)) * 3;
                p0 = ph[0]; p1 = ph[1]; p2 = ph[2];
                jjb = (sq & 15) << 6;
            }
#pragma unroll
            for (int ni = 0; ni < 4; ni++) {
                const int n = n0 + wn * 32 + ni * 8 + 2 * gc;
                float v0 = c[mi][ni][h2 * 2 + 0] + bias[n];
                float v1 = c[mi][ni][h2 * 2 + 1] + bias[n + 1];
                if (do_phys) {
                    const int j0 = jjb + (n & 63);
                    v0 += pbv * (p0 * Pw[j0]     + p1 * Pw[1024 + j0]     + p2 * Pw[2048 + j0]);
                    v1 += pbv * (p0 * Pw[j0 + 1] + p1 * Pw[1024 + j0 + 1] + p2 * Pw[2048 + j0 + 1]);
                }
                if (out_half) {
                    *(unsigned*)&((__half*)Cout)[(size_t)m * DIM + n] =
                        f2h2(v0 * oscale, v1 * oscale);
                } else {
                    *(float2*)&((float*)Cout)[(size_t)m * DIM + n] = make_float2(v0, v1);
                }
            }
        }
    }
}

// ---------------------------------------------------------------------------
// FP16 flash attention (unchanged from R13/R15, ~528 TF/s).
// ---------------------------------------------------------------------------
#define AQ_OFF 0
#define AK_OFF 9216
#define AV_OFF 13824
#define A_SMEM_BYTES ((13824 + 64 * 72) * 2)   // 36864

__global__ __launch_bounds__(256, 2)
void attn_f16(const __half* __restrict__ Q, const __half* __restrict__ K,
              const __half* __restrict__ Vt, __half* __restrict__ O) {
    extern __shared__ __half sm_h[];
    __half* Qs = sm_h + AQ_OFF;
    __half* Ks = sm_h + AK_OFF;
    __half* Vs = sm_h + AV_OFF;
    const unsigned sQ = (unsigned)__cvta_generic_to_shared(Qs);
    const unsigned sK = (unsigned)__cvta_generic_to_shared(Ks);
    const unsigned sV = (unsigned)__cvta_generic_to_shared(Vs);

    const int t    = threadIdx.x;
    const int w    = t >> 5;
    const int lane = t & 31;
    const int gr   = lane >> 2;
    const int gc   = lane & 3;
    const int qw   = w * 16;
    const int qb   = blockIdx.x;
    const int h    = blockIdx.y;
    const int b    = blockIdx.z;
    const int q0   = qb * 128;

    const unsigned offA = ((((lane & 7) + ((lane & 8) ? 8 : 0)) * 72) +
                           ((lane & 16) ? 8 : 0)) * 2;
    const unsigned offB = (((((lane >> 4) * 8) + (lane & 7)) * 72) +
                           ((lane & 8) ? 8 : 0)) * 2;

    const __half* Qg  = Q  + ((size_t)(b * SEQ + q0)) * DIM + h * DKH;
    const __half* Kg  = K  + ((size_t)b * SEQ) * DIM + h * DKH;
    const __half* Vtg = Vt + (size_t)(b * DIM + h * DKH) * SEQ;

#pragma unroll
    for (int i = 0; i < 4; i++) {
        const int cq = t + i * 256;
        const int r = cq >> 3, d = (cq & 7) * 8;
        cpa16(sQ + (r * 72 + d) * 2, Qg + (size_t)r * DIM + d);
    }
    cpa_commit();

    auto issueK = [&](int kt) {
#pragma unroll
        for (int i = 0; i < 2; i++) {
            const int cc = t + i * 256;
            const int r = cc >> 3, d = (cc & 7) * 8;
            cpa16(sK + (r * 72 + d) * 2, Kg + (size_t)(kt * 64 + r) * DIM + d);
        }
        cpa_commit();
    };
    auto issueV = [&](int kt) {
#pragma unroll
        for (int i = 0; i < 2; i++) {
            const int cc = t + i * 256;
            const int r = cc >> 3, d = (cc & 7) * 8;
            cpa16(sV + (r * 72 + d) * 2, Vtg + (size_t)r * SEQ + kt * 64 + d);
        }
        cpa_commit();
    };

    issueK(0);
    issueV(0);

    float m0 = -1e30f, m1 = -1e30f, l0 = 0.f, l1 = 0.f;
    float o[8][4];
#pragma unroll
    for (int di = 0; di < 8; di++)
#pragma unroll
        for (int r = 0; r < 4; r++) o[di][r] = 0.f;

    for (int kt = 0; kt < SEQ / 64; kt++) {
        asm volatile("cp.async.wait_group 0;");
        __syncthreads();

        float s[8][4];
#pragma unroll
        for (int ni = 0; ni < 8; ni++)
#pragma unroll
            for (int r = 0; r < 4; r++) s[ni][r] = 0.f;
#pragma unroll
        for (int ks = 0; ks < 4; ks++) {
            const int ko = ks * 16;
            unsigned a0, a1, a2, a3;
            ldsm_x4(a0, a1, a2, a3, sQ + (qw * 72 + ko) * 2 + offA);
            unsigned bfr[8][2];
#pragma unroll
            for (int j = 0; j < 4; j++)
                ldsm_x4(bfr[2 * j][0], bfr[2 * j][1], bfr[2 * j + 1][0], bfr[2 * j + 1][1],
                        sK + ((j * 16) * 72 + ko) * 2 + offB);
#pragma unroll
            for (int ni = 0; ni < 8; ni++)
                mma_f16(s[ni], a0, a1, a2, a3, bfr[ni][0], bfr[ni][1]);
        }
        __syncthreads();
        if (kt + 1 < SEQ / 64) issueK(kt + 1);

        float mx0 = -1e30f, mx1 = -1e30f;
#pragma unroll
        for (int ni = 0; ni < 8; ni++) {
            mx0 = fmaxf(mx0, fmaxf(s[ni][0], s[ni][1]));
            mx1 = fmaxf(mx1, fmaxf(s[ni][2], s[ni][3]));
        }
        mx0 = fmaxf(mx0, __shfl_xor_sync(0xffffffffu, mx0, 1));
        mx0 = fmaxf(mx0, __shfl_xor_sync(0xffffffffu, mx0, 2));
        mx1 = fmaxf(mx1, __shfl_xor_sync(0xffffffffu, mx1, 1));
        mx1 = fmaxf(mx1, __shfl_xor_sync(0xffffffffu, mx1, 2));
        const float mn0 = fmaxf(m0, mx0), mn1 = fmaxf(m1, mx1);
        const float al0 = __expf(m0 - mn0), al1 = __expf(m1 - mn1);
        m0 = mn0; m1 = mn1;
        float rs0 = 0.f, rs1 = 0.f;
#pragma unroll
        for (int ni = 0; ni < 8; ni++) {
            s[ni][0] = __expf(s[ni][0] - mn0);
            s[ni][1] = __expf(s[ni][1] - mn0);
            s[ni][2] = __expf(s[ni][2] - mn1);
            s[ni][3] = __expf(s[ni][3] - mn1);
            rs0 += s[ni][0] + s[ni][1];
            rs1 += s[ni][2] + s[ni][3];
        }
        rs0 += __shfl_xor_sync(0xffffffffu, rs0, 1);
        rs0 += __shfl_xor_sync(0xffffffffu, rs0, 2);
        rs1 += __shfl_xor_sync(0xffffffffu, rs1, 1);
        rs1 += __shfl_xor_sync(0xffffffffu, rs1, 2);
        l0 = l0 * al0 + rs0;
        l1 = l1 * al1 + rs1;

        unsigned pl[8], ph[8];
#pragma unroll
        for (int ni = 0; ni < 8; ni++) {
            pl[ni] = f2h2(s[ni][0], s[ni][1]);
            ph[ni] = f2h2(s[ni][2], s[ni][3]);
        }
#pragma unroll
        for (int di = 0; di < 8; di++) {
            o[di][0] *= al0; o[di][1] *= al0;
            o[di][2] *= al1; o[di][3] *= al1;
        }

#pragma unroll
        for (int ks = 0; ks < 4; ks++) {
            const int ko = ks * 16;
            const unsigned a0 = pl[2 * ks];
            const unsigned a1 = ph[2 * ks];
            const unsigned a2 = pl[2 * ks + 1];
            const unsigned a3 = ph[2 * ks + 1];
            unsigned bfr[8][2];
#pragma unroll
            for (int j = 0; j < 4; j++)
                ldsm_x4(bfr[2 * j][0], bfr[2 * j][1], bfr[2 * j + 1][0], bfr[2 * j + 1][1],
                        sV + ((j * 16) * 72 + ko) * 2 + offB);
#pragma unroll
            for (int di = 0; di < 8; di++)
                mma_f16(o[di], a0, a1, a2, a3, bfr[di][0], bfr[di][1]);
        }
        __syncthreads();
        if (kt + 1 < SEQ / 64) issueV(kt + 1);
    }

    const float i0 = 1.f / l0, i1 = 1.f / l1;
    const size_t r0 = (size_t)(b * SEQ + q0 + qw + gr) * DIM + h * DKH;
    const size_t r1 = (size_t)(b * SEQ + q0 + qw + gr + 8) * DIM + h * DKH;
#pragma unroll
    for (int di = 0; di < 8; di++) {
        const int col = di * 8 + 2 * gc;
        *(unsigned*)&O[r0 + col] = f2h2(o[di][0] * i0, o[di][1] * i0);
        *(unsigned*)&O[r1 + col] = f2h2(o[di][2] * i1, o[di][3] * i1);
    }
}

// ---------------------------------------------------------------------------
// Launch
// ---------------------------------------------------------------------------
extern "C" void kernel_launch(void* const* d_in, const int* in_sizes, int n_in,
                              void* d_out, int out_size) {
    const float* query  = (const float*)d_in[0];
    const float* key_in = (const float*)d_in[1];
    const float* value  = (const float*)d_in[2];
    const float* phys   = (const float*)d_in[3];
    const float* bq     = (const float*)d_in[5];
    const float* bk     = (const float*)d_in[7];
    const float* bv     = (const float*)d_in[9];
    const float* bo     = (const float*)d_in[11];
    const float* Pw     = (const float*)d_in[12];
    const float* pb     = (const float*)d_in[13];
    float* out          = (float*)d_out;

    __half *pQ, *pK, *pV, *pVt, *pC, *hA0, *hA1, *hA2, *hW;
    cudaGetSymbolAddress((void**)&pQ,  g_Qh);
    cudaGetSymbolAddress((void**)&pK,  g_Kh);
    cudaGetSymbolAddress((void**)&pV,  g_Vh);
    cudaGetSymbolAddress((void**)&pVt, g_Vt);
    cudaGetSymbolAddress((void**)&pC,  g_Ch);
    cudaGetSymbolAddress((void**)&hA0, g_hA0);
    cudaGetSymbolAddress((void**)&hA1, g_hA1);
    cudaGetSymbolAddress((void**)&hA2, g_hA2);
    cudaGetSymbolAddress((void**)&hW,  g_hWt);

    cudaFuncSetAttribute(gemm_f16_batched, cudaFuncAttributeMaxDynamicSharedMemorySize,
                         G_SMEM_BYTES);
    cudaFuncSetAttribute(attn_f16, cudaFuncAttributeMaxDynamicSharedMemorySize,
                         A_SMEM_BYTES);

    // Pre-convert inputs (fp16) and weights (transpose + fp16)
    cvt3_kernel<<<dim3(NELEM / 1024, 3), 256>>>(query, key_in, value, hA0, hA1, hA2);
    cvtWT_kernel<<<dim3(32, 32, 4), dim3(32, 8)>>>(
        (const float*)d_in[4], (const float*)d_in[6], (const float*)d_in[8],
        (const float*)d_in[10], hW);

    // Merged Q/K/V projections: 768 CTAs fill the chip
    dim3 gq(DIM / 128, MROWS / 128, 3);   // (8, 32, 3)
    gemm_f16_batched<<<gq, 256, G_SMEM_BYTES>>>(
        hA0, hA1, hA2, hW, bq, bk, bv, pQ, pK, pV, 1, 0.125f, phys, Pw, pb);

    // V -> V^T (dk-major) for attention GEMM2 B-operand
    transposeV_kernel<<<dim3(SEQ / 32, DIM / 32, 2), dim3(32, 8)>>>(pV, pVt);

    dim3 ga(SEQ / 128, HEADS, 2);         // (16, 16, 2)
    attn_f16<<<ga, 256, A_SMEM_BYTES>>>(pQ, pK, pVt, pC);

    // Output projection (fp32 out), z-dim of 1 reusing the batched kernel
    dim3 go(DIM / 128, MROWS / 128, 1);
    gemm_f16_batched<<<go, 256, G_SMEM_BYTES>>>(
        pC, pC, pC, hW + 3 * WELEM, bo, bo, bo, out, out, out, 0, 1.0f,
        nullptr, nullptr, nullptr);
}